// round 9
// baseline (speedup 1.0000x reference)
#include <cuda_runtime.h>
#include <cstdint>
#include <math.h>

// Problem constants
#define BB   2
#define NN   2000
#define GG   100
#define HH   800
#define WW   800
#define TT   200
#define PP   66
#define NEGN 134
#define MH   28
#define MW   28

// d_out float32 layout (flattened tuple concat):
#define BASE_ROI 0
#define BASE_CLS (BB*TT*4)
#define BASE_DLT (BASE_CLS + BB*TT)
#define BASE_MSK (BASE_DLT + BB*TT*4)

// Fused-kernel block map
#define NB_IOU    64        // blocks 0..63
#define BLK_DET   64        // block 64
#define NB_PRE    65        // iou + detect
#define BLK_SEL0  65        // blocks 65..68
#define NB_SEL    4
#define BLK_MSK0  69        // blocks 69..468
#define NB_TOTAL  (BLK_MSK0 + BB*TT)   // 469

typedef unsigned long long ull;

// Scratch (no device allocation allowed -> __device__ globals)
__device__ int   g_mask_mode;
__device__ int   g_sel_ok[BB*PP];
__device__ int   g_sel_gt[BB*PP];
__device__ float g_sel_box[BB*PP*4];
__device__ float g_miou[BB*NN];
__device__ float g_cmax[BB*NN];
__device__ int   g_asn [BB*NN];

// Spin gates (reset to 0 by the last-finishing block each run -> replay-safe)
__device__ int   g_done_iou;
__device__ int   g_done_sel;
__device__ int   g_done_all;

__device__ __forceinline__ unsigned int float_ord(float f) {
    unsigned int u = __float_as_uint(f);
    return (u & 0x80000000u) ? ~u : (u | 0x80000000u);
}
__device__ __forceinline__ float ord_to_float(unsigned int k) {
    unsigned int u = (k & 0x80000000u) ? (k ^ 0x80000000u) : ~k;
    return __uint_as_float(u);
}
__device__ __forceinline__ ull umax64(ull a, ull b) { return a > b ? a : b; }
__device__ __forceinline__ ull umin64(ull a, ull b) { return a > b ? b : a; }

__device__ __forceinline__ void gate_wait(volatile int* cnt, int target) {
    // called by thread 0 only; caller does __syncthreads after
    while (*cnt < target) __nanosleep(64);
}

// ---------------------------------------------------------------------------
// In-warp bitonic sort of 256 u64 keys (k[8]/lane, elem = rr*32+lane), DESC.
// ---------------------------------------------------------------------------
__device__ __forceinline__ void cas_pair(ull& a, ull& b, bool desc) {
    ull hi = umax64(a, b), lo = umin64(a, b);
    a = desc ? hi : lo;  b = desc ? lo : hi;
}

__device__ __forceinline__ void warp_sort256_desc(ull k[8], int lane) {
    #pragma unroll
    for (int kk = 2; kk <= 256; kk <<= 1) {
        #pragma unroll
        for (int j = kk >> 1; j >= 32; j >>= 1) {
            const int rj = j >> 5;
            #pragma unroll
            for (int rr = 0; rr < 8; rr++) if ((rr & rj) == 0) {
                bool desc = (((rr*32) & kk) == 0);
                cas_pair(k[rr], k[rr | rj], desc);
            }
        }
        #pragma unroll
        for (int j = (kk >> 1) < 32 ? (kk >> 1) : 16; j >= 1; j >>= 1) {
            #pragma unroll
            for (int rr = 0; rr < 8; rr++) {
                ull p = __shfl_xor_sync(0xFFFFFFFFu, k[rr], j);
                bool desc = (((rr*32 + lane) & kk) == 0);
                bool up = ((lane & j) == 0);
                k[rr] = (up == desc) ? umax64(k[rr], p) : umin64(k[rr], p);
            }
        }
    }
}

__device__ __forceinline__ void warp_merge256_desc(ull k[8], int lane) {
    #pragma unroll
    for (int j = 128; j >= 32; j >>= 1) {
        const int rj = j >> 5;
        #pragma unroll
        for (int rr = 0; rr < 8; rr++) if ((rr & rj) == 0)
            cas_pair(k[rr], k[rr | rj], true);
    }
    #pragma unroll
    for (int j = 16; j >= 1; j >>= 1) {
        #pragma unroll
        for (int rr = 0; rr < 8; rr++) {
            ull p = __shfl_xor_sync(0xFFFFFFFFu, k[rr], j);
            bool up = ((lane & j) == 0);
            k[rr] = up ? umax64(k[rr], p) : umin64(k[rr], p);
        }
    }
}

// ---------------------------------------------------------------------------
// Phase bodies
// ---------------------------------------------------------------------------
__device__ void do_iou(int blk, const float* __restrict__ props,
                       const int* __restrict__ cls, const float* __restrict__ boxes)
{
    const int b    = blk >> 5;          // 32 blocks per image
    const int blkx = blk & 31;
    const int t = threadIdx.x;
    const int lane = t & 31;
    const int sub  = lane & 3;
    const int n    = blkx * 64 + (t >> 2);

    __shared__ float4 s_gt[GG];
    __shared__ int    s_cls[GG];
    if (t < GG)                   s_gt[t]      = ((const float4*)boxes)[b*GG + t];
    if (t >= 128 && t < 128 + GG) s_cls[t-128] = cls[b*GG + (t-128)];
    __syncthreads();

    if (n < NN) {
        const float4 pb = ((const float4*)props)[b*NN + n];
        const float py1 = pb.x, px1 = pb.y, py2 = pb.z, px2 = pb.w;
        const float a1 = (py2 - py1) * (px2 - px1);

        ull bestkey = 0ull;
        float cmax = -1.0f;
        #pragma unroll
        for (int g = sub; g < GG; g += 4) {
            float4 gb = s_gt[g];
            float yy1 = fmaxf(py1, gb.x), xx1 = fmaxf(px1, gb.y);
            float yy2 = fminf(py2, gb.z), xx2 = fminf(px2, gb.w);
            float ih = fmaxf(yy2 - yy1, 0.0f);
            float iw = fmaxf(xx2 - xx1, 0.0f);
            float inter = ih * iw;
            float a2 = (gb.z - gb.x) * (gb.w - gb.y);
            float uni = a1 + a2 - inter;
            float iou = inter / fmaxf(uni, 1e-12f);
            bool crowd = (s_cls[g] < 0);
            float ov = crowd ? -1.0f : iou;
            ull key = ((ull)float_ord(ov) << 32) |
                      (unsigned int)(0xFFFFFFFFu - (unsigned int)g);
            bestkey = umax64(bestkey, key);
            cmax = fmaxf(cmax, crowd ? iou : -1.0f);
        }
        bestkey = umax64(bestkey, __shfl_xor_sync(0xFFFFFFFFu, bestkey, 1));
        cmax    = fmaxf(cmax,     __shfl_xor_sync(0xFFFFFFFFu, cmax,    1));
        bestkey = umax64(bestkey, __shfl_xor_sync(0xFFFFFFFFu, bestkey, 2));
        cmax    = fmaxf(cmax,     __shfl_xor_sync(0xFFFFFFFFu, cmax,    2));

        if (sub == 0) {
            g_miou[b*NN + n] = ord_to_float((unsigned int)(bestkey >> 32));
            g_asn [b*NN + n] = (int)(0xFFFFFFFFu - (unsigned int)(bestkey & 0xFFFFFFFFull));
            g_cmax[b*NN + n] = cmax;
        }
    }
    __syncthreads();
    __threadfence();
    if (threadIdx.x == 0) atomicAdd(&g_done_iou, 1);
}

__device__ void do_detect(const void* __restrict__ masks)
{
    if (threadIdx.x < 32) {
        const uint4* w4 = (const uint4*)masks;
        bool weird = false, sawF = false;
        for (int i = threadIdx.x; i < 512; i += 32) {
            uint4 v = w4[i];
            #define CHK(x) { unsigned int u = (x); \
                if (u == 0x3F800000u) sawF = true; \
                else if (u != 0u && u != 1u) weird = true; }
            CHK(v.x) CHK(v.y) CHK(v.z) CHK(v.w)
            #undef CHK
        }
        weird = __any_sync(0xFFFFFFFFu, weird);
        sawF  = __any_sync(0xFFFFFFFFu, sawF);
        if (threadIdx.x == 0) {
            g_mask_mode = weird ? 0 : (sawF ? 1 : 2);
            __threadfence();
            atomicAdd(&g_done_iou, 1);
        }
    }
}

__device__ void do_select(int sblk, const float* __restrict__ props,
                          const int* __restrict__ cls, const float* __restrict__ boxes,
                          float* __restrict__ out)
{
    const int b    = sblk >> 1;
    const int role = sblk & 1;
    const int t    = threadIdx.x;
    const int lane = t & 31, w = t >> 5;

    __shared__ ull sA[2048];
    __shared__ ull sB[1024];
    __shared__ ull sC[512];
    __shared__ ull sF[256];

    // gate on all iou + detect done
    if (t == 0) gate_wait(&g_done_iou, NB_PRE);
    __syncthreads();
    __threadfence();

    ull k[8];
    #pragma unroll
    for (int rr = 0; rr < 8; rr++) {
        int n = w*256 + rr*32 + lane;
        ull key = 0ull;
        if (n < NN) {
            float v;
            float m = g_miou[b*NN + n];
            if (role == 0) {
                v = (m >= 0.5f) ? m : -1.0f;
            } else {
                bool neg = (m < 0.5f) && (g_cmax[b*NN + n] < 0.001f);
                v = neg ? m : -1.0f;
            }
            key = ((ull)float_ord(v) << 32) |
                  (unsigned int)(0xFFFFFFFFu - (unsigned int)n);
        }
        k[rr] = key;
    }
    warp_sort256_desc(k, lane);
    #pragma unroll
    for (int rr = 0; rr < 8; rr++) sA[w*256 + rr*32 + lane] = k[rr];
    __syncthreads();

    if (w < 4) {
        #pragma unroll
        for (int rr = 0; rr < 8; rr++) {
            int e = rr*32 + lane;
            k[rr] = umax64(sA[w*512 + e], sA[w*512 + 256 + (255 - e)]);
        }
        warp_merge256_desc(k, lane);
        #pragma unroll
        for (int rr = 0; rr < 8; rr++) sB[w*256 + rr*32 + lane] = k[rr];
    }
    __syncthreads();

    if (w < 2) {
        #pragma unroll
        for (int rr = 0; rr < 8; rr++) {
            int e = rr*32 + lane;
            k[rr] = umax64(sB[w*512 + e], sB[w*512 + 256 + (255 - e)]);
        }
        warp_merge256_desc(k, lane);
        #pragma unroll
        for (int rr = 0; rr < 8; rr++) sC[w*256 + rr*32 + lane] = k[rr];
    }
    __syncthreads();

    if (w == 0) {
        #pragma unroll
        for (int rr = 0; rr < 8; rr++) {
            int e = rr*32 + lane;
            k[rr] = umax64(sC[e], sC[256 + (255 - e)]);
        }
        warp_merge256_desc(k, lane);
        #pragma unroll
        for (int rr = 0; rr < 8; rr++) sF[rr*32 + lane] = k[rr];
    }
    __syncthreads();

    if (role == 0) {
        if (t < PP) {
            int i = t;
            int n = (int)(0xFFFFFFFFu - (unsigned int)sF[i]);
            float m = g_miou[b*NN + n];
            bool ok = (m >= 0.5f);
            int g = g_asn[b*NN + n];
            const float4 pb = ((const float4*)props)[b*NN + n];
            float q0 = pb.x, q1 = pb.y, q2 = pb.z, q3 = pb.w;
            int oT = b*TT + i;

            out[BASE_ROI + oT*4 + 0] = ok ? q0 : 0.0f;
            out[BASE_ROI + oT*4 + 1] = ok ? q1 : 0.0f;
            out[BASE_ROI + oT*4 + 2] = ok ? q2 : 0.0f;
            out[BASE_ROI + oT*4 + 3] = ok ? q3 : 0.0f;
            out[BASE_CLS + oT] = ok ? (float)cls[b*GG + g] : 0.0f;

            float d0=0.f, d1=0.f, d2=0.f, d3=0.f;
            if (ok) {
                float h  = q2 - q0, wd = q3 - q1;
                float cy = q0 + 0.5f*h, cx = q1 + 0.5f*wd;
                float gy1 = boxes[b*GG*4 + g*4+0], gx1 = boxes[b*GG*4 + g*4+1];
                float gy2 = boxes[b*GG*4 + g*4+2], gx2 = boxes[b*GG*4 + g*4+3];
                float gh = gy2 - gy1, gw = gx2 - gx1;
                float gcy = gy1 + 0.5f*gh, gcx = gx1 + 0.5f*gw;
                d0 = ((gcy - cy) / h) / 0.1f;
                d1 = ((gcx - cx) / wd) / 0.1f;
                d2 = logf(gh / h) / 0.2f;
                d3 = logf(gw / wd) / 0.2f;
            }
            out[BASE_DLT + oT*4 + 0] = d0;
            out[BASE_DLT + oT*4 + 1] = d1;
            out[BASE_DLT + oT*4 + 2] = d2;
            out[BASE_DLT + oT*4 + 3] = d3;

            int s = b*PP + i;
            g_sel_ok[s]      = ok ? 1 : 0;
            g_sel_gt[s]      = g;
            g_sel_box[s*4+0] = q0;
            g_sel_box[s*4+1] = q1;
            g_sel_box[s*4+2] = q2;
            g_sel_box[s*4+3] = q3;
        }
    } else {
        if (t < NEGN) {
            int i = t;
            int n = (int)(0xFFFFFFFFu - (unsigned int)sF[i]);
            float m = g_miou[b*NN + n];
            bool ok = (m < 0.5f) && (g_cmax[b*NN + n] < 0.001f);
            const float4 pb = ((const float4*)props)[b*NN + n];
            int oT = b*TT + PP + i;
            out[BASE_ROI + oT*4 + 0] = ok ? pb.x : 0.0f;
            out[BASE_ROI + oT*4 + 1] = ok ? pb.y : 0.0f;
            out[BASE_ROI + oT*4 + 2] = ok ? pb.z : 0.0f;
            out[BASE_ROI + oT*4 + 3] = ok ? pb.w : 0.0f;
            out[BASE_CLS + oT] = 0.0f;
            out[BASE_DLT + oT*4 + 0] = 0.0f;
            out[BASE_DLT + oT*4 + 1] = 0.0f;
            out[BASE_DLT + oT*4 + 2] = 0.0f;
            out[BASE_DLT + oT*4 + 3] = 0.0f;
        }
    }
    __syncthreads();
    __threadfence();
    if (t == 0) atomicAdd(&g_done_sel, 1);
}

// Mask crop-resize: VALIDATED bit-exact path — all rn intrinsics, no FMA.
__device__ __forceinline__ float read_mask(const void* m, int mode, int b, int y, int x, int g) {
    size_t idx = (((size_t)b*HH + y)*WW + x)*GG + g;
    if (mode == 0) return ((const unsigned char*)m)[idx] ? 1.0f : 0.0f;
    if (mode == 1) return ((const float*)m)[idx];
    return (float)((const int*)m)[idx];
}

__device__ void do_mask(int bt, const void* __restrict__ masks, float* __restrict__ out)
{
    const int b = bt / TT, t = bt % TT;
    float* mout = out + BASE_MSK + (size_t)bt * (MH*MW);

    if (t >= PP) {   // negatives: no dependency, write immediately
        for (int i = threadIdx.x; i < MH*MW; i += blockDim.x) mout[i] = 0.0f;
        return;
    }

    // positives: wait for select
    if (threadIdx.x == 0) gate_wait(&g_done_sel, NB_SEL);
    __syncthreads();
    __threadfence();

    if (!g_sel_ok[b*PP + t]) {
        for (int i = threadIdx.x; i < MH*MW; i += blockDim.x) mout[i] = 0.0f;
        return;
    }
    const int s = b*PP + t;
    const int g = g_sel_gt[s];
    const float by1 = g_sel_box[s*4+0], bx1 = g_sel_box[s*4+1];
    const float by2 = g_sel_box[s*4+2], bx2 = g_sel_box[s*4+3];
    const int mode = g_mask_mode;

    const float dy = __fsub_rn(by2, by1);
    const float dx = __fsub_rn(bx2, bx1);
    const float baseY = __fmul_rn(by1, (float)(HH-1));
    const float baseX = __fmul_rn(bx1, (float)(WW-1));

    for (int i = threadIdx.x; i < MH*MW; i += blockDim.x) {
        int py = i / MW, px = i % MW;
        float ty = __fdiv_rn((float)py, (float)(MH-1));
        float ys = __fadd_rn(baseY, __fmul_rn(__fmul_rn(ty, dy), (float)(HH-1)));
        float tx = __fdiv_rn((float)px, (float)(MW-1));
        float xs = __fadd_rn(baseX, __fmul_rn(__fmul_rn(tx, dx), (float)(WW-1)));

        float y0f = floorf(ys), x0f = floorf(xs);
        float wy = __fsub_rn(ys, y0f);
        float wx = __fsub_rn(xs, x0f);
        int y0 = min(max((int)y0f, 0), HH-1);
        int y1 = min(y0 + 1, HH-1);
        int x0 = min(max((int)x0f, 0), WW-1);
        int x1 = min(x0 + 1, WW-1);

        float v00 = read_mask(masks, mode, b, y0, x0, g);
        float v01 = read_mask(masks, mode, b, y0, x1, g);
        float v10 = read_mask(masks, mode, b, y1, x0, g);
        float v11 = read_mask(masks, mode, b, y1, x1, g);

        float omwx = __fsub_rn(1.0f, wx);
        float omwy = __fsub_rn(1.0f, wy);
        float top = __fadd_rn(__fmul_rn(v00, omwx), __fmul_rn(v01, wx));
        float bot = __fadd_rn(__fmul_rn(v10, omwx), __fmul_rn(v11, wx));
        float v   = __fadd_rn(__fmul_rn(top, omwy), __fmul_rn(bot, wy));
        mout[i] = rintf(v);   // jnp.round = half-to-even
    }
}

// ---------------------------------------------------------------------------
// Fused kernel
// ---------------------------------------------------------------------------
__global__ void __launch_bounds__(256) fused_kernel(
    const float* __restrict__ props,
    const int*   __restrict__ cls,
    const float* __restrict__ boxes,
    const void*  __restrict__ masks,
    float*       __restrict__ out)
{
    const int blk = blockIdx.x;

    if (blk < NB_IOU) {
        do_iou(blk, props, cls, boxes);
    } else if (blk == BLK_DET) {
        do_detect(masks);
    } else if (blk < BLK_SEL0 + NB_SEL) {
        do_select(blk - BLK_SEL0, props, cls, boxes, out);
    } else {
        do_mask(blk - BLK_MSK0, masks, out);
    }

    // run-completion bookkeeping: last block resets the gates for replay
    __syncthreads();
    if (threadIdx.x == 0) {
        __threadfence();
        int r = atomicAdd(&g_done_all, 1);
        if (r == NB_TOTAL - 1) {
            g_done_iou = 0;
            g_done_sel = 0;
            g_done_all = 0;
        }
    }
}

// ---------------------------------------------------------------------------
extern "C" void kernel_launch(void* const* d_in, const int* in_sizes, int n_in,
                              void* d_out, int out_size)
{
    const float* props = (const float*)d_in[0];   // (B,N,4)
    const int*   cls   = (const int*)  d_in[1];   // (B,G)
    const float* boxes = (const float*)d_in[2];   // (B,G,4)
    const void*  masks = d_in[3];                 // (B,H,W,G)

    float* out = (float*)d_out;

    fused_kernel<<<NB_TOTAL, 256>>>(props, cls, boxes, masks, out);
}

// round 10
// speedup vs baseline: 1.1293x; 1.1293x over previous
#include <cuda_runtime.h>
#include <cstdint>
#include <math.h>

// Problem constants
#define BB   2
#define NN   2000
#define GG   100
#define HH   800
#define WW   800
#define TT   200
#define PP   66
#define NEGN 134
#define MH   28
#define MW   28

// d_out float32 layout (flattened tuple concat):
#define BASE_ROI 0
#define BASE_CLS (BB*TT*4)
#define BASE_DLT (BASE_CLS + BB*TT)
#define BASE_MSK (BASE_DLT + BB*TT*4)

// Phase-1 kernel block map
#define NB_IOU    64        // blocks 0..63  (32 per image)
#define BLK_DET   64        // block 64
#define BLK_SEL0  65        // blocks 65..68
#define NB_SEL    4
#define NB_P1     (BLK_SEL0 + NB_SEL)   // 69

typedef unsigned long long ull;

// Scratch (no device allocation allowed -> __device__ globals)
__device__ int   g_mask_mode;
__device__ int   g_sel_ok[BB*PP];
__device__ int   g_sel_gt[BB*PP];
__device__ float g_sel_box[BB*PP*4];
__device__ float g_miou[BB*NN];
__device__ float g_cmax[BB*NN];
__device__ int   g_asn [BB*NN];

// Gates (reset by last select block each run -> replay-safe)
__device__ int   g_done_iou;
__device__ int   g_done_sel;

__device__ __forceinline__ unsigned int float_ord(float f) {
    unsigned int u = __float_as_uint(f);
    return (u & 0x80000000u) ? ~u : (u | 0x80000000u);
}
__device__ __forceinline__ float ord_to_float(unsigned int k) {
    unsigned int u = (k & 0x80000000u) ? (k ^ 0x80000000u) : ~k;
    return __uint_as_float(u);
}
__device__ __forceinline__ ull umax64(ull a, ull b) { return a > b ? a : b; }
__device__ __forceinline__ ull umin64(ull a, ull b) { return a > b ? b : a; }

// ---------------------------------------------------------------------------
// In-warp bitonic sort of 256 u64 keys (k[8]/lane, elem = rr*32+lane), DESC.
// ---------------------------------------------------------------------------
__device__ __forceinline__ void cas_pair(ull& a, ull& b, bool desc) {
    ull hi = umax64(a, b), lo = umin64(a, b);
    a = desc ? hi : lo;  b = desc ? lo : hi;
}

__device__ __forceinline__ void warp_sort256_desc(ull k[8], int lane) {
    #pragma unroll
    for (int kk = 2; kk <= 256; kk <<= 1) {
        #pragma unroll
        for (int j = kk >> 1; j >= 32; j >>= 1) {
            const int rj = j >> 5;
            #pragma unroll
            for (int rr = 0; rr < 8; rr++) if ((rr & rj) == 0) {
                bool desc = (((rr*32) & kk) == 0);
                cas_pair(k[rr], k[rr | rj], desc);
            }
        }
        #pragma unroll
        for (int j = (kk >> 1) < 32 ? (kk >> 1) : 16; j >= 1; j >>= 1) {
            #pragma unroll
            for (int rr = 0; rr < 8; rr++) {
                ull p = __shfl_xor_sync(0xFFFFFFFFu, k[rr], j);
                bool desc = (((rr*32 + lane) & kk) == 0);
                bool up = ((lane & j) == 0);
                k[rr] = (up == desc) ? umax64(k[rr], p) : umin64(k[rr], p);
            }
        }
    }
}

__device__ __forceinline__ void warp_merge256_desc(ull k[8], int lane) {
    #pragma unroll
    for (int j = 128; j >= 32; j >>= 1) {
        const int rj = j >> 5;
        #pragma unroll
        for (int rr = 0; rr < 8; rr++) if ((rr & rj) == 0)
            cas_pair(k[rr], k[rr | rj], true);
    }
    #pragma unroll
    for (int j = 16; j >= 1; j >>= 1) {
        #pragma unroll
        for (int rr = 0; rr < 8; rr++) {
            ull p = __shfl_xor_sync(0xFFFFFFFFu, k[rr], j);
            bool up = ((lane & j) == 0);
            k[rr] = up ? umax64(k[rr], p) : umin64(k[rr], p);
        }
    }
}

// ---------------------------------------------------------------------------
// Phase-1 kernel: iou (blocks 0..63) + dtype detect (64) + select (65..68).
// Only the 4 select blocks spin, and only for the short iou duration.
// ---------------------------------------------------------------------------
__global__ void __launch_bounds__(256) phase1_kernel(
    const float* __restrict__ props,   // (B,N,4)
    const int*   __restrict__ cls,     // (B,G)
    const float* __restrict__ boxes,   // (B,G,4)
    const void*  __restrict__ masks,
    float*       __restrict__ out)
{
    const int blk = blockIdx.x;
    const int t = threadIdx.x;

    if (blk < NB_IOU) {
        // ---- IoU: 4 lanes per proposal, 64 proposals/block ----
        const int b    = blk >> 5;
        const int blkx = blk & 31;
        const int lane = t & 31;
        const int sub  = lane & 3;
        const int n    = blkx * 64 + (t >> 2);

        __shared__ float4 s_gt[GG];
        __shared__ int    s_cls[GG];
        if (t < GG)                   s_gt[t]      = ((const float4*)boxes)[b*GG + t];
        if (t >= 128 && t < 128 + GG) s_cls[t-128] = cls[b*GG + (t-128)];
        __syncthreads();

        if (n < NN) {
            const float4 pb = ((const float4*)props)[b*NN + n];
            const float py1 = pb.x, px1 = pb.y, py2 = pb.z, px2 = pb.w;
            const float a1 = (py2 - py1) * (px2 - px1);

            ull bestkey = 0ull;
            float cmax = -1.0f;
            #pragma unroll
            for (int g = sub; g < GG; g += 4) {
                float4 gb = s_gt[g];
                float yy1 = fmaxf(py1, gb.x), xx1 = fmaxf(px1, gb.y);
                float yy2 = fminf(py2, gb.z), xx2 = fminf(px2, gb.w);
                float ih = fmaxf(yy2 - yy1, 0.0f);
                float iw = fmaxf(xx2 - xx1, 0.0f);
                float inter = ih * iw;
                float a2 = (gb.z - gb.x) * (gb.w - gb.y);
                float uni = a1 + a2 - inter;
                float iou = inter / fmaxf(uni, 1e-12f);
                bool crowd = (s_cls[g] < 0);
                float ov = crowd ? -1.0f : iou;
                ull key = ((ull)float_ord(ov) << 32) |
                          (unsigned int)(0xFFFFFFFFu - (unsigned int)g);
                bestkey = umax64(bestkey, key);
                cmax = fmaxf(cmax, crowd ? iou : -1.0f);
            }
            bestkey = umax64(bestkey, __shfl_xor_sync(0xFFFFFFFFu, bestkey, 1));
            cmax    = fmaxf(cmax,     __shfl_xor_sync(0xFFFFFFFFu, cmax,    1));
            bestkey = umax64(bestkey, __shfl_xor_sync(0xFFFFFFFFu, bestkey, 2));
            cmax    = fmaxf(cmax,     __shfl_xor_sync(0xFFFFFFFFu, cmax,    2));

            if (sub == 0) {
                g_miou[b*NN + n] = ord_to_float((unsigned int)(bestkey >> 32));
                g_asn [b*NN + n] = (int)(0xFFFFFFFFu - (unsigned int)(bestkey & 0xFFFFFFFFull));
                g_cmax[b*NN + n] = cmax;
            }
        }
        __syncthreads();
        __threadfence();
        if (t == 0) atomicAdd(&g_done_iou, 1);
        return;
    }

    if (blk == BLK_DET) {
        if (t < 32) {
            const uint4* w4 = (const uint4*)masks;
            bool weird = false, sawF = false;
            for (int i = t; i < 512; i += 32) {
                uint4 v = w4[i];
                #define CHK(x) { unsigned int u = (x); \
                    if (u == 0x3F800000u) sawF = true; \
                    else if (u != 0u && u != 1u) weird = true; }
                CHK(v.x) CHK(v.y) CHK(v.z) CHK(v.w)
                #undef CHK
            }
            weird = __any_sync(0xFFFFFFFFu, weird);
            sawF  = __any_sync(0xFFFFFFFFu, sawF);
            if (t == 0) g_mask_mode = weird ? 0 : (sawF ? 1 : 2);
        }
        return;
    }

    // ---- select blocks ----
    {
        const int sblk = blk - BLK_SEL0;
        const int b    = sblk >> 1;
        const int role = sblk & 1;
        const int lane = t & 31, w = t >> 5;

        __shared__ ull sA[2048];
        __shared__ ull sB[1024];
        __shared__ ull sC[512];
        __shared__ ull sF[256];

        if (t == 0) {
            volatile int* cnt = &g_done_iou;
            while (*cnt < NB_IOU) __nanosleep(32);
        }
        __syncthreads();
        __threadfence();

        ull k[8];
        #pragma unroll
        for (int rr = 0; rr < 8; rr++) {
            int n = w*256 + rr*32 + lane;
            ull key = 0ull;
            if (n < NN) {
                float v;
                float m = g_miou[b*NN + n];
                if (role == 0) {
                    v = (m >= 0.5f) ? m : -1.0f;
                } else {
                    bool neg = (m < 0.5f) && (g_cmax[b*NN + n] < 0.001f);
                    v = neg ? m : -1.0f;
                }
                key = ((ull)float_ord(v) << 32) |
                      (unsigned int)(0xFFFFFFFFu - (unsigned int)n);
            }
            k[rr] = key;
        }
        warp_sort256_desc(k, lane);
        #pragma unroll
        for (int rr = 0; rr < 8; rr++) sA[w*256 + rr*32 + lane] = k[rr];
        __syncthreads();

        if (w < 4) {
            #pragma unroll
            for (int rr = 0; rr < 8; rr++) {
                int e = rr*32 + lane;
                k[rr] = umax64(sA[w*512 + e], sA[w*512 + 256 + (255 - e)]);
            }
            warp_merge256_desc(k, lane);
            #pragma unroll
            for (int rr = 0; rr < 8; rr++) sB[w*256 + rr*32 + lane] = k[rr];
        }
        __syncthreads();

        if (w < 2) {
            #pragma unroll
            for (int rr = 0; rr < 8; rr++) {
                int e = rr*32 + lane;
                k[rr] = umax64(sB[w*512 + e], sB[w*512 + 256 + (255 - e)]);
            }
            warp_merge256_desc(k, lane);
            #pragma unroll
            for (int rr = 0; rr < 8; rr++) sC[w*256 + rr*32 + lane] = k[rr];
        }
        __syncthreads();

        if (w == 0) {
            #pragma unroll
            for (int rr = 0; rr < 8; rr++) {
                int e = rr*32 + lane;
                k[rr] = umax64(sC[e], sC[256 + (255 - e)]);
            }
            warp_merge256_desc(k, lane);
            #pragma unroll
            for (int rr = 0; rr < 8; rr++) sF[rr*32 + lane] = k[rr];
        }
        __syncthreads();

        if (role == 0) {
            if (t < PP) {
                int i = t;
                int n = (int)(0xFFFFFFFFu - (unsigned int)sF[i]);
                float m = g_miou[b*NN + n];
                bool ok = (m >= 0.5f);
                int g = g_asn[b*NN + n];
                const float4 pb = ((const float4*)props)[b*NN + n];
                float q0 = pb.x, q1 = pb.y, q2 = pb.z, q3 = pb.w;
                int oT = b*TT + i;

                out[BASE_ROI + oT*4 + 0] = ok ? q0 : 0.0f;
                out[BASE_ROI + oT*4 + 1] = ok ? q1 : 0.0f;
                out[BASE_ROI + oT*4 + 2] = ok ? q2 : 0.0f;
                out[BASE_ROI + oT*4 + 3] = ok ? q3 : 0.0f;
                out[BASE_CLS + oT] = ok ? (float)cls[b*GG + g] : 0.0f;

                float d0=0.f, d1=0.f, d2=0.f, d3=0.f;
                if (ok) {
                    float h  = q2 - q0, wd = q3 - q1;
                    float cy = q0 + 0.5f*h, cx = q1 + 0.5f*wd;
                    float gy1 = boxes[b*GG*4 + g*4+0], gx1 = boxes[b*GG*4 + g*4+1];
                    float gy2 = boxes[b*GG*4 + g*4+2], gx2 = boxes[b*GG*4 + g*4+3];
                    float gh = gy2 - gy1, gw = gx2 - gx1;
                    float gcy = gy1 + 0.5f*gh, gcx = gx1 + 0.5f*gw;
                    d0 = ((gcy - cy) / h) / 0.1f;
                    d1 = ((gcx - cx) / wd) / 0.1f;
                    d2 = logf(gh / h) / 0.2f;
                    d3 = logf(gw / wd) / 0.2f;
                }
                out[BASE_DLT + oT*4 + 0] = d0;
                out[BASE_DLT + oT*4 + 1] = d1;
                out[BASE_DLT + oT*4 + 2] = d2;
                out[BASE_DLT + oT*4 + 3] = d3;

                int s = b*PP + i;
                g_sel_ok[s]      = ok ? 1 : 0;
                g_sel_gt[s]      = g;
                g_sel_box[s*4+0] = q0;
                g_sel_box[s*4+1] = q1;
                g_sel_box[s*4+2] = q2;
                g_sel_box[s*4+3] = q3;
            }
        } else {
            if (t < NEGN) {
                int i = t;
                int n = (int)(0xFFFFFFFFu - (unsigned int)sF[i]);
                float m = g_miou[b*NN + n];
                bool ok = (m < 0.5f) && (g_cmax[b*NN + n] < 0.001f);
                const float4 pb = ((const float4*)props)[b*NN + n];
                int oT = b*TT + PP + i;
                out[BASE_ROI + oT*4 + 0] = ok ? pb.x : 0.0f;
                out[BASE_ROI + oT*4 + 1] = ok ? pb.y : 0.0f;
                out[BASE_ROI + oT*4 + 2] = ok ? pb.z : 0.0f;
                out[BASE_ROI + oT*4 + 3] = ok ? pb.w : 0.0f;
                out[BASE_CLS + oT] = 0.0f;
                out[BASE_DLT + oT*4 + 0] = 0.0f;
                out[BASE_DLT + oT*4 + 1] = 0.0f;
                out[BASE_DLT + oT*4 + 2] = 0.0f;
                out[BASE_DLT + oT*4 + 3] = 0.0f;
            }
        }
        __syncthreads();
        if (t == 0) {
            __threadfence();
            int r = atomicAdd(&g_done_sel, 1);
            if (r == NB_SEL - 1) {         // last select block resets gates
                g_done_iou = 0;
                g_done_sel = 0;
            }
        }
    }
}

// ---------------------------------------------------------------------------
// Phase-2 kernel: mask crop-resize. One block per (b,t), one THREAD per pixel.
// VALIDATED bit-exact arithmetic — all rn intrinsics, no FMA contraction.
// ---------------------------------------------------------------------------
__device__ __forceinline__ float read_mask(const void* m, int mode, int b, int y, int x, int g) {
    size_t idx = (((size_t)b*HH + y)*WW + x)*GG + g;
    if (mode == 0) return ((const unsigned char*)m)[idx] ? 1.0f : 0.0f;
    if (mode == 1) return ((const float*)m)[idx];
    return (float)((const int*)m)[idx];
}

__global__ void __launch_bounds__(784) mask_kernel(const void* __restrict__ masks,
                                                   float* __restrict__ out)
{
    const int bt = blockIdx.x;
    const int b = bt / TT, t = bt % TT;
    float* mout = out + BASE_MSK + (size_t)bt * (MH*MW);
    const int i = threadIdx.x;           // 0..783, one pixel each

    if (t >= PP || !g_sel_ok[b*PP + t]) {
        mout[i] = 0.0f;
        return;
    }
    const int s = b*PP + t;
    const int g = g_sel_gt[s];
    const float by1 = g_sel_box[s*4+0], bx1 = g_sel_box[s*4+1];
    const float by2 = g_sel_box[s*4+2], bx2 = g_sel_box[s*4+3];
    const int mode = g_mask_mode;

    const float dy = __fsub_rn(by2, by1);
    const float dx = __fsub_rn(bx2, bx1);
    const float baseY = __fmul_rn(by1, (float)(HH-1));
    const float baseX = __fmul_rn(bx1, (float)(WW-1));

    int py = i / MW, px = i % MW;
    float ty = __fdiv_rn((float)py, (float)(MH-1));
    float ys = __fadd_rn(baseY, __fmul_rn(__fmul_rn(ty, dy), (float)(HH-1)));
    float tx = __fdiv_rn((float)px, (float)(MW-1));
    float xs = __fadd_rn(baseX, __fmul_rn(__fmul_rn(tx, dx), (float)(WW-1)));

    float y0f = floorf(ys), x0f = floorf(xs);
    float wy = __fsub_rn(ys, y0f);
    float wx = __fsub_rn(xs, x0f);
    int y0 = min(max((int)y0f, 0), HH-1);
    int y1 = min(y0 + 1, HH-1);
    int x0 = min(max((int)x0f, 0), WW-1);
    int x1 = min(x0 + 1, WW-1);

    float v00 = read_mask(masks, mode, b, y0, x0, g);
    float v01 = read_mask(masks, mode, b, y0, x1, g);
    float v10 = read_mask(masks, mode, b, y1, x0, g);
    float v11 = read_mask(masks, mode, b, y1, x1, g);

    float omwx = __fsub_rn(1.0f, wx);
    float omwy = __fsub_rn(1.0f, wy);
    float top = __fadd_rn(__fmul_rn(v00, omwx), __fmul_rn(v01, wx));
    float bot = __fadd_rn(__fmul_rn(v10, omwx), __fmul_rn(v11, wx));
    float v   = __fadd_rn(__fmul_rn(top, omwy), __fmul_rn(bot, wy));
    mout[i] = rintf(v);   // jnp.round = half-to-even
}

// ---------------------------------------------------------------------------
extern "C" void kernel_launch(void* const* d_in, const int* in_sizes, int n_in,
                              void* d_out, int out_size)
{
    const float* props = (const float*)d_in[0];   // (B,N,4)
    const int*   cls   = (const int*)  d_in[1];   // (B,G)
    const float* boxes = (const float*)d_in[2];   // (B,G,4)
    const void*  masks = d_in[3];                 // (B,H,W,G)

    float* out = (float*)d_out;

    phase1_kernel<<<NB_P1, 256>>>(props, cls, boxes, masks, out);
    mask_kernel<<<BB*TT, 784>>>(masks, out);
}

// round 11
// speedup vs baseline: 1.2281x; 1.0875x over previous
#include <cuda_runtime.h>
#include <cstdint>
#include <math.h>

// Problem constants
#define BB   2
#define NN   2000
#define GG   100
#define HH   800
#define WW   800
#define TT   200
#define PP   66
#define NEGN 134
#define MH   28
#define MW   28

// d_out float32 layout (flattened tuple concat):
#define BASE_ROI 0
#define BASE_CLS (BB*TT*4)
#define BASE_DLT (BASE_CLS + BB*TT)
#define BASE_MSK (BASE_DLT + BB*TT*4)

typedef unsigned long long ull;

// Scratch (no device allocation allowed -> __device__ globals)
__device__ int   g_mask_mode;
__device__ int   g_sel_ok[BB*PP];
__device__ int   g_sel_gt[BB*PP];
__device__ float g_sel_box[BB*PP*4];
__device__ float g_miou[BB*NN];
__device__ float g_cmax[BB*NN];
__device__ int   g_asn [BB*NN];

__device__ __forceinline__ unsigned int float_ord(float f) {
    unsigned int u = __float_as_uint(f);
    return (u & 0x80000000u) ? ~u : (u | 0x80000000u);
}
__device__ __forceinline__ float ord_to_float(unsigned int k) {
    unsigned int u = (k & 0x80000000u) ? (k ^ 0x80000000u) : ~k;
    return __uint_as_float(u);
}
__device__ __forceinline__ ull umax64(ull a, ull b) { return a > b ? a : b; }
__device__ __forceinline__ ull umin64(ull a, ull b) { return a > b ? b : a; }

// ---------------------------------------------------------------------------
// Kernel A: IoU (4 lanes/proposal) + dtype detect. Triggers PDL early so the
// select kernel's launch overlaps this kernel's execution.
//   grid = (33, BB): block (32,0) -> dtype detection, (32,1) -> noop.
// ---------------------------------------------------------------------------
__global__ void __launch_bounds__(256) iou_kernel(
    const float* __restrict__ props,   // (B,N,4)
    const int*   __restrict__ cls,     // (B,G)
    const float* __restrict__ boxes,   // (B,G,4)
    const void*  __restrict__ masks)
{
    if (threadIdx.x == 0) cudaTriggerProgrammaticLaunchCompletion();

    if (blockIdx.x == 32) {
        if (blockIdx.y == 0 && threadIdx.x < 32) {
            const uint4* w4 = (const uint4*)masks;
            bool weird = false, sawF = false;
            for (int i = threadIdx.x; i < 512; i += 32) {   // 8KB sample
                uint4 v = w4[i];
                #define CHK(x) { unsigned int u = (x); \
                    if (u == 0x3F800000u) sawF = true; \
                    else if (u != 0u && u != 1u) weird = true; }
                CHK(v.x) CHK(v.y) CHK(v.z) CHK(v.w)
                #undef CHK
            }
            weird = __any_sync(0xFFFFFFFFu, weird);
            sawF  = __any_sync(0xFFFFFFFFu, sawF);
            if (threadIdx.x == 0) g_mask_mode = weird ? 0 : (sawF ? 1 : 2);
        }
        return;
    }

    const int b = blockIdx.y;
    const int t = threadIdx.x;
    const int lane = t & 31;
    const int sub  = lane & 3;
    const int n    = blockIdx.x * 64 + (t >> 2);

    __shared__ float4 s_gt[GG];
    __shared__ int    s_cls[GG];
    if (t < GG)                   s_gt[t]      = ((const float4*)boxes)[b*GG + t];
    if (t >= 128 && t < 128 + GG) s_cls[t-128] = cls[b*GG + (t-128)];
    __syncthreads();

    if (n >= NN) return;

    const float4 pb = ((const float4*)props)[b*NN + n];
    const float py1 = pb.x, px1 = pb.y, py2 = pb.z, px2 = pb.w;
    const float a1 = (py2 - py1) * (px2 - px1);

    ull bestkey = 0ull;
    float cmax = -1.0f;
    #pragma unroll
    for (int g = sub; g < GG; g += 4) {        // 25 iterations
        float4 gb = s_gt[g];
        float yy1 = fmaxf(py1, gb.x), xx1 = fmaxf(px1, gb.y);
        float yy2 = fminf(py2, gb.z), xx2 = fminf(px2, gb.w);
        float ih = fmaxf(yy2 - yy1, 0.0f);
        float iw = fmaxf(xx2 - xx1, 0.0f);
        float inter = ih * iw;
        float a2 = (gb.z - gb.x) * (gb.w - gb.y);
        float uni = a1 + a2 - inter;
        float iou = inter / fmaxf(uni, 1e-12f);
        bool crowd = (s_cls[g] < 0);
        float ov = crowd ? -1.0f : iou;
        ull key = ((ull)float_ord(ov) << 32) |
                  (unsigned int)(0xFFFFFFFFu - (unsigned int)g);
        bestkey = umax64(bestkey, key);
        cmax = fmaxf(cmax, crowd ? iou : -1.0f);
    }
    bestkey = umax64(bestkey, __shfl_xor_sync(0xFFFFFFFFu, bestkey, 1));
    cmax    = fmaxf(cmax,     __shfl_xor_sync(0xFFFFFFFFu, cmax,    1));
    bestkey = umax64(bestkey, __shfl_xor_sync(0xFFFFFFFFu, bestkey, 2));
    cmax    = fmaxf(cmax,     __shfl_xor_sync(0xFFFFFFFFu, cmax,    2));

    if (sub == 0) {
        g_miou[b*NN + n] = ord_to_float((unsigned int)(bestkey >> 32));
        g_asn [b*NN + n] = (int)(0xFFFFFFFFu - (unsigned int)(bestkey & 0xFFFFFFFFull));
        g_cmax[b*NN + n] = cmax;
    }
}

// ---------------------------------------------------------------------------
// In-warp bitonic sort of 256 u64 keys (k[8]/lane, elem = rr*32+lane), DESC.
// ---------------------------------------------------------------------------
__device__ __forceinline__ void cas_pair(ull& a, ull& b, bool desc) {
    ull hi = umax64(a, b), lo = umin64(a, b);
    a = desc ? hi : lo;  b = desc ? lo : hi;
}

__device__ __forceinline__ void warp_sort256_desc(ull k[8], int lane) {
    #pragma unroll
    for (int kk = 2; kk <= 256; kk <<= 1) {
        #pragma unroll
        for (int j = kk >> 1; j >= 32; j >>= 1) {
            const int rj = j >> 5;
            #pragma unroll
            for (int rr = 0; rr < 8; rr++) if ((rr & rj) == 0) {
                bool desc = (((rr*32) & kk) == 0);
                cas_pair(k[rr], k[rr | rj], desc);
            }
        }
        #pragma unroll
        for (int j = (kk >> 1) < 32 ? (kk >> 1) : 16; j >= 1; j >>= 1) {
            #pragma unroll
            for (int rr = 0; rr < 8; rr++) {
                ull p = __shfl_xor_sync(0xFFFFFFFFu, k[rr], j);
                bool desc = (((rr*32 + lane) & kk) == 0);
                bool up = ((lane & j) == 0);
                k[rr] = (up == desc) ? umax64(k[rr], p) : umin64(k[rr], p);
            }
        }
    }
}

__device__ __forceinline__ void warp_merge256_desc(ull k[8], int lane) {
    #pragma unroll
    for (int j = 128; j >= 32; j >>= 1) {
        const int rj = j >> 5;
        #pragma unroll
        for (int rr = 0; rr < 8; rr++) if ((rr & rj) == 0)
            cas_pair(k[rr], k[rr | rj], true);
    }
    #pragma unroll
    for (int j = 16; j >= 1; j >>= 1) {
        #pragma unroll
        for (int rr = 0; rr < 8; rr++) {
            ull p = __shfl_xor_sync(0xFFFFFFFFu, k[rr], j);
            bool up = ((lane & j) == 0);
            k[rr] = up ? umax64(k[rr], p) : umin64(k[rr], p);
        }
    }
}

// ---------------------------------------------------------------------------
// Kernel B: top-k select + output writes. PDL secondary of iou_kernel:
// launches early, then cudaGridDependencySynchronize() waits for iou grid.
// ---------------------------------------------------------------------------
__global__ void __launch_bounds__(256) select_kernel(
    const float* __restrict__ props,
    const int*   __restrict__ cls,
    const float* __restrict__ boxes,
    float*       __restrict__ out)
{
    if (threadIdx.x == 0) cudaTriggerProgrammaticLaunchCompletion();

    const int b    = blockIdx.x >> 1;
    const int role = blockIdx.x & 1;          // 0 = positives, 1 = negatives
    const int t    = threadIdx.x;
    const int lane = t & 31, w = t >> 5;

    __shared__ ull sA[2048];
    __shared__ ull sB[1024];
    __shared__ ull sC[512];
    __shared__ ull sF[256];

    cudaGridDependencySynchronize();   // wait for iou grid (all threads)

    ull k[8];
    #pragma unroll
    for (int rr = 0; rr < 8; rr++) {
        int n = w*256 + rr*32 + lane;
        ull key = 0ull;
        if (n < NN) {
            float v;
            float m = g_miou[b*NN + n];
            if (role == 0) {
                v = (m >= 0.5f) ? m : -1.0f;
            } else {
                bool neg = (m < 0.5f) && (g_cmax[b*NN + n] < 0.001f);
                v = neg ? m : -1.0f;
            }
            key = ((ull)float_ord(v) << 32) |
                  (unsigned int)(0xFFFFFFFFu - (unsigned int)n);
        }
        k[rr] = key;
    }
    warp_sort256_desc(k, lane);
    #pragma unroll
    for (int rr = 0; rr < 8; rr++) sA[w*256 + rr*32 + lane] = k[rr];
    __syncthreads();

    if (w < 4) {
        #pragma unroll
        for (int rr = 0; rr < 8; rr++) {
            int e = rr*32 + lane;
            k[rr] = umax64(sA[w*512 + e], sA[w*512 + 256 + (255 - e)]);
        }
        warp_merge256_desc(k, lane);
        #pragma unroll
        for (int rr = 0; rr < 8; rr++) sB[w*256 + rr*32 + lane] = k[rr];
    }
    __syncthreads();

    if (w < 2) {
        #pragma unroll
        for (int rr = 0; rr < 8; rr++) {
            int e = rr*32 + lane;
            k[rr] = umax64(sB[w*512 + e], sB[w*512 + 256 + (255 - e)]);
        }
        warp_merge256_desc(k, lane);
        #pragma unroll
        for (int rr = 0; rr < 8; rr++) sC[w*256 + rr*32 + lane] = k[rr];
    }
    __syncthreads();

    if (w == 0) {
        #pragma unroll
        for (int rr = 0; rr < 8; rr++) {
            int e = rr*32 + lane;
            k[rr] = umax64(sC[e], sC[256 + (255 - e)]);
        }
        warp_merge256_desc(k, lane);
        #pragma unroll
        for (int rr = 0; rr < 8; rr++) sF[rr*32 + lane] = k[rr];
    }
    __syncthreads();

    if (role == 0) {
        if (t < PP) {
            int i = t;
            int n = (int)(0xFFFFFFFFu - (unsigned int)sF[i]);
            float m = g_miou[b*NN + n];
            bool ok = (m >= 0.5f);
            int g = g_asn[b*NN + n];
            const float4 pb = ((const float4*)props)[b*NN + n];
            float q0 = pb.x, q1 = pb.y, q2 = pb.z, q3 = pb.w;
            int oT = b*TT + i;

            out[BASE_ROI + oT*4 + 0] = ok ? q0 : 0.0f;
            out[BASE_ROI + oT*4 + 1] = ok ? q1 : 0.0f;
            out[BASE_ROI + oT*4 + 2] = ok ? q2 : 0.0f;
            out[BASE_ROI + oT*4 + 3] = ok ? q3 : 0.0f;
            out[BASE_CLS + oT] = ok ? (float)cls[b*GG + g] : 0.0f;

            float d0=0.f, d1=0.f, d2=0.f, d3=0.f;
            if (ok) {
                float h  = q2 - q0, wd = q3 - q1;
                float cy = q0 + 0.5f*h, cx = q1 + 0.5f*wd;
                float gy1 = boxes[b*GG*4 + g*4+0], gx1 = boxes[b*GG*4 + g*4+1];
                float gy2 = boxes[b*GG*4 + g*4+2], gx2 = boxes[b*GG*4 + g*4+3];
                float gh = gy2 - gy1, gw = gx2 - gx1;
                float gcy = gy1 + 0.5f*gh, gcx = gx1 + 0.5f*gw;
                d0 = ((gcy - cy) / h) / 0.1f;
                d1 = ((gcx - cx) / wd) / 0.1f;
                d2 = logf(gh / h) / 0.2f;
                d3 = logf(gw / wd) / 0.2f;
            }
            out[BASE_DLT + oT*4 + 0] = d0;
            out[BASE_DLT + oT*4 + 1] = d1;
            out[BASE_DLT + oT*4 + 2] = d2;
            out[BASE_DLT + oT*4 + 3] = d3;

            int s = b*PP + i;
            g_sel_ok[s]      = ok ? 1 : 0;
            g_sel_gt[s]      = g;
            g_sel_box[s*4+0] = q0;
            g_sel_box[s*4+1] = q1;
            g_sel_box[s*4+2] = q2;
            g_sel_box[s*4+3] = q3;
        }
    } else {
        if (t < NEGN) {
            int i = t;
            int n = (int)(0xFFFFFFFFu - (unsigned int)sF[i]);
            float m = g_miou[b*NN + n];
            bool ok = (m < 0.5f) && (g_cmax[b*NN + n] < 0.001f);
            const float4 pb = ((const float4*)props)[b*NN + n];
            int oT = b*TT + PP + i;
            out[BASE_ROI + oT*4 + 0] = ok ? pb.x : 0.0f;
            out[BASE_ROI + oT*4 + 1] = ok ? pb.y : 0.0f;
            out[BASE_ROI + oT*4 + 2] = ok ? pb.z : 0.0f;
            out[BASE_ROI + oT*4 + 3] = ok ? pb.w : 0.0f;
            out[BASE_CLS + oT] = 0.0f;
            out[BASE_DLT + oT*4 + 0] = 0.0f;
            out[BASE_DLT + oT*4 + 1] = 0.0f;
            out[BASE_DLT + oT*4 + 2] = 0.0f;
            out[BASE_DLT + oT*4 + 3] = 0.0f;
        }
    }
}

// ---------------------------------------------------------------------------
// Kernel C: mask crop-resize. PDL secondary of select_kernel. Negative tiles
// write zeros with NO dependency (run concurrently with iou/select); positive
// tiles cudaGridDependencySynchronize() first.
// VALIDATED bit-exact arithmetic — all rn intrinsics, no FMA contraction.
// ---------------------------------------------------------------------------
__device__ __forceinline__ float read_mask(const void* m, int mode, int b, int y, int x, int g) {
    size_t idx = (((size_t)b*HH + y)*WW + x)*GG + g;
    if (mode == 0) return ((const unsigned char*)m)[idx] ? 1.0f : 0.0f;
    if (mode == 1) return ((const float*)m)[idx];
    return (float)((const int*)m)[idx];
}

__global__ void __launch_bounds__(784) mask_kernel(const void* __restrict__ masks,
                                                   float* __restrict__ out)
{
    const int bt = blockIdx.x;
    const int b = bt / TT, t = bt % TT;
    float* mout = out + BASE_MSK + (size_t)bt * (MH*MW);
    const int i = threadIdx.x;           // 0..783, one pixel each

    if (t >= PP) {                       // negatives: no dependency at all
        mout[i] = 0.0f;
        return;
    }

    cudaGridDependencySynchronize();     // wait for select grid (all threads)

    if (!g_sel_ok[b*PP + t]) {
        mout[i] = 0.0f;
        return;
    }
    const int s = b*PP + t;
    const int g = g_sel_gt[s];
    const float by1 = g_sel_box[s*4+0], bx1 = g_sel_box[s*4+1];
    const float by2 = g_sel_box[s*4+2], bx2 = g_sel_box[s*4+3];
    const int mode = g_mask_mode;

    const float dy = __fsub_rn(by2, by1);
    const float dx = __fsub_rn(bx2, bx1);
    const float baseY = __fmul_rn(by1, (float)(HH-1));
    const float baseX = __fmul_rn(bx1, (float)(WW-1));

    int py = i / MW, px = i % MW;
    float ty = __fdiv_rn((float)py, (float)(MH-1));
    float ys = __fadd_rn(baseY, __fmul_rn(__fmul_rn(ty, dy), (float)(HH-1)));
    float tx = __fdiv_rn((float)px, (float)(MW-1));
    float xs = __fadd_rn(baseX, __fmul_rn(__fmul_rn(tx, dx), (float)(WW-1)));

    float y0f = floorf(ys), x0f = floorf(xs);
    float wy = __fsub_rn(ys, y0f);
    float wx = __fsub_rn(xs, x0f);
    int y0 = min(max((int)y0f, 0), HH-1);
    int y1 = min(y0 + 1, HH-1);
    int x0 = min(max((int)x0f, 0), WW-1);
    int x1 = min(x0 + 1, WW-1);

    float v00 = read_mask(masks, mode, b, y0, x0, g);
    float v01 = read_mask(masks, mode, b, y0, x1, g);
    float v10 = read_mask(masks, mode, b, y1, x0, g);
    float v11 = read_mask(masks, mode, b, y1, x1, g);

    float omwx = __fsub_rn(1.0f, wx);
    float omwy = __fsub_rn(1.0f, wy);
    float top = __fadd_rn(__fmul_rn(v00, omwx), __fmul_rn(v01, wx));
    float bot = __fadd_rn(__fmul_rn(v10, omwx), __fmul_rn(v11, wx));
    float v   = __fadd_rn(__fmul_rn(top, omwy), __fmul_rn(bot, wy));
    mout[i] = rintf(v);   // jnp.round = half-to-even
}

// ---------------------------------------------------------------------------
extern "C" void kernel_launch(void* const* d_in, const int* in_sizes, int n_in,
                              void* d_out, int out_size)
{
    const float* props = (const float*)d_in[0];   // (B,N,4)
    const int*   cls   = (const int*)  d_in[1];   // (B,G)
    const float* boxes = (const float*)d_in[2];   // (B,G,4)
    const void*  masks = d_in[3];                 // (B,H,W,G)

    float* out = (float*)d_out;

    // K1: plain launch
    dim3 gridA(33, BB);
    iou_kernel<<<gridA, 256>>>(props, cls, boxes, masks);

    // K2: PDL secondary of K1
    {
        cudaLaunchConfig_t cfg = {};
        cfg.gridDim  = dim3(4, 1, 1);
        cfg.blockDim = dim3(256, 1, 1);
        cfg.stream   = 0;
        cudaLaunchAttribute a[1];
        a[0].id = cudaLaunchAttributeProgrammaticStreamSerialization;
        a[0].val.programmaticStreamSerializationAllowed = 1;
        cfg.attrs = a;
        cfg.numAttrs = 1;
        cudaLaunchKernelEx(&cfg, select_kernel, props, cls, boxes, out);
    }

    // K3: PDL secondary of K2 (negative tiles run with no dependency)
    {
        cudaLaunchConfig_t cfg = {};
        cfg.gridDim  = dim3(BB*TT, 1, 1);
        cfg.blockDim = dim3(784, 1, 1);
        cfg.stream   = 0;
        cudaLaunchAttribute a[1];
        a[0].id = cudaLaunchAttributeProgrammaticStreamSerialization;
        a[0].val.programmaticStreamSerializationAllowed = 1;
        cfg.attrs = a;
        cfg.numAttrs = 1;
        cudaLaunchKernelEx(&cfg, mask_kernel, masks, out);
    }
}

// round 12
// speedup vs baseline: 1.3269x; 1.0805x over previous
#include <cuda_runtime.h>
#include <cstdint>
#include <math.h>

// Problem constants
#define BB   2
#define NN   2000
#define GG   100
#define HH   800
#define WW   800
#define TT   200
#define PP   66
#define NEGN 134
#define MH   28
#define MW   28

// d_out float32 layout (flattened tuple concat):
#define BASE_ROI 0
#define BASE_CLS (BB*TT*4)
#define BASE_DLT (BASE_CLS + BB*TT)
#define BASE_MSK (BASE_DLT + BB*TT*4)

// mask kernel split: 2 blocks per tile, 392 px each
#define MSPLIT 2
#define MPX    (MH*MW/MSPLIT)   // 392

typedef unsigned long long ull;

// Scratch (no device allocation allowed -> __device__ globals)
__device__ int   g_mask_mode;
__device__ int   g_sel_ok[BB*PP];
__device__ int   g_sel_gt[BB*PP];
__device__ float g_sel_box[BB*PP*4];
__device__ float g_miou[BB*NN];
__device__ float g_cmax[BB*NN];
__device__ int   g_asn [BB*NN];

__device__ __forceinline__ unsigned int float_ord(float f) {
    unsigned int u = __float_as_uint(f);
    return (u & 0x80000000u) ? ~u : (u | 0x80000000u);
}
__device__ __forceinline__ float ord_to_float(unsigned int k) {
    unsigned int u = (k & 0x80000000u) ? (k ^ 0x80000000u) : ~k;
    return __uint_as_float(u);
}
__device__ __forceinline__ ull umax64(ull a, ull b) { return a > b ? a : b; }
__device__ __forceinline__ ull umin64(ull a, ull b) { return a > b ? b : a; }

// ---------------------------------------------------------------------------
// Kernel A: IoU (4 lanes/proposal) + dtype detect. PDL primary.
//   grid = (33, BB): block (32,0) -> dtype detection, (32,1) -> noop.
// ---------------------------------------------------------------------------
__global__ void __launch_bounds__(256) iou_kernel(
    const float* __restrict__ props,   // (B,N,4)
    const int*   __restrict__ cls,     // (B,G)
    const float* __restrict__ boxes,   // (B,G,4)
    const void*  __restrict__ masks)
{
    if (threadIdx.x == 0) cudaTriggerProgrammaticLaunchCompletion();

    if (blockIdx.x == 32) {
        if (blockIdx.y == 0 && threadIdx.x < 32) {
            const uint4* w4 = (const uint4*)masks;
            bool weird = false, sawF = false;
            for (int i = threadIdx.x; i < 512; i += 32) {   // 8KB sample
                uint4 v = w4[i];
                #define CHK(x) { unsigned int u = (x); \
                    if (u == 0x3F800000u) sawF = true; \
                    else if (u != 0u && u != 1u) weird = true; }
                CHK(v.x) CHK(v.y) CHK(v.z) CHK(v.w)
                #undef CHK
            }
            weird = __any_sync(0xFFFFFFFFu, weird);
            sawF  = __any_sync(0xFFFFFFFFu, sawF);
            if (threadIdx.x == 0) g_mask_mode = weird ? 0 : (sawF ? 1 : 2);
        }
        return;
    }

    const int b = blockIdx.y;
    const int t = threadIdx.x;
    const int lane = t & 31;
    const int sub  = lane & 3;
    const int n    = blockIdx.x * 64 + (t >> 2);

    __shared__ float4 s_gt[GG];
    __shared__ int    s_cls[GG];
    if (t < GG)                   s_gt[t]      = ((const float4*)boxes)[b*GG + t];
    if (t >= 128 && t < 128 + GG) s_cls[t-128] = cls[b*GG + (t-128)];
    __syncthreads();

    if (n >= NN) return;

    const float4 pb = ((const float4*)props)[b*NN + n];
    const float py1 = pb.x, px1 = pb.y, py2 = pb.z, px2 = pb.w;
    const float a1 = (py2 - py1) * (px2 - px1);

    ull bestkey = 0ull;
    float cmax = -1.0f;
    #pragma unroll
    for (int g = sub; g < GG; g += 4) {        // 25 iterations
        float4 gb = s_gt[g];
        float yy1 = fmaxf(py1, gb.x), xx1 = fmaxf(px1, gb.y);
        float yy2 = fminf(py2, gb.z), xx2 = fminf(px2, gb.w);
        float ih = fmaxf(yy2 - yy1, 0.0f);
        float iw = fmaxf(xx2 - xx1, 0.0f);
        float inter = ih * iw;
        float a2 = (gb.z - gb.x) * (gb.w - gb.y);
        float uni = a1 + a2 - inter;
        float iou = inter / fmaxf(uni, 1e-12f);
        bool crowd = (s_cls[g] < 0);
        float ov = crowd ? -1.0f : iou;
        ull key = ((ull)float_ord(ov) << 32) |
                  (unsigned int)(0xFFFFFFFFu - (unsigned int)g);
        bestkey = umax64(bestkey, key);
        cmax = fmaxf(cmax, crowd ? iou : -1.0f);
    }
    bestkey = umax64(bestkey, __shfl_xor_sync(0xFFFFFFFFu, bestkey, 1));
    cmax    = fmaxf(cmax,     __shfl_xor_sync(0xFFFFFFFFu, cmax,    1));
    bestkey = umax64(bestkey, __shfl_xor_sync(0xFFFFFFFFu, bestkey, 2));
    cmax    = fmaxf(cmax,     __shfl_xor_sync(0xFFFFFFFFu, cmax,    2));

    if (sub == 0) {
        g_miou[b*NN + n] = ord_to_float((unsigned int)(bestkey >> 32));
        g_asn [b*NN + n] = (int)(0xFFFFFFFFu - (unsigned int)(bestkey & 0xFFFFFFFFull));
        g_cmax[b*NN + n] = cmax;
    }
}

// ---------------------------------------------------------------------------
// In-warp bitonic sort of 256 u64 keys (k[8]/lane, elem = rr*32+lane), DESC.
// ---------------------------------------------------------------------------
__device__ __forceinline__ void cas_pair(ull& a, ull& b, bool desc) {
    ull hi = umax64(a, b), lo = umin64(a, b);
    a = desc ? hi : lo;  b = desc ? lo : hi;
}

__device__ __forceinline__ void warp_sort256_desc(ull k[8], int lane) {
    #pragma unroll
    for (int kk = 2; kk <= 256; kk <<= 1) {
        #pragma unroll
        for (int j = kk >> 1; j >= 32; j >>= 1) {
            const int rj = j >> 5;
            #pragma unroll
            for (int rr = 0; rr < 8; rr++) if ((rr & rj) == 0) {
                bool desc = (((rr*32) & kk) == 0);
                cas_pair(k[rr], k[rr | rj], desc);
            }
        }
        #pragma unroll
        for (int j = (kk >> 1) < 32 ? (kk >> 1) : 16; j >= 1; j >>= 1) {
            #pragma unroll
            for (int rr = 0; rr < 8; rr++) {
                ull p = __shfl_xor_sync(0xFFFFFFFFu, k[rr], j);
                bool desc = (((rr*32 + lane) & kk) == 0);
                bool up = ((lane & j) == 0);
                k[rr] = (up == desc) ? umax64(k[rr], p) : umin64(k[rr], p);
            }
        }
    }
}

__device__ __forceinline__ void warp_merge256_desc(ull k[8], int lane) {
    #pragma unroll
    for (int j = 128; j >= 32; j >>= 1) {
        const int rj = j >> 5;
        #pragma unroll
        for (int rr = 0; rr < 8; rr++) if ((rr & rj) == 0)
            cas_pair(k[rr], k[rr | rj], true);
    }
    #pragma unroll
    for (int j = 16; j >= 1; j >>= 1) {
        #pragma unroll
        for (int rr = 0; rr < 8; rr++) {
            ull p = __shfl_xor_sync(0xFFFFFFFFu, k[rr], j);
            bool up = ((lane & j) == 0);
            k[rr] = up ? umax64(k[rr], p) : umin64(k[rr], p);
        }
    }
}

// ---------------------------------------------------------------------------
// Kernel B: top-k select + output writes. PDL secondary of iou_kernel.
// ---------------------------------------------------------------------------
__global__ void __launch_bounds__(256) select_kernel(
    const float* __restrict__ props,
    const int*   __restrict__ cls,
    const float* __restrict__ boxes,
    float*       __restrict__ out)
{
    if (threadIdx.x == 0) cudaTriggerProgrammaticLaunchCompletion();

    const int b    = blockIdx.x >> 1;
    const int role = blockIdx.x & 1;          // 0 = positives, 1 = negatives
    const int t    = threadIdx.x;
    const int lane = t & 31, w = t >> 5;

    __shared__ ull sA[2048];
    __shared__ ull sB[1024];
    __shared__ ull sC[512];
    __shared__ ull sF[256];

    cudaGridDependencySynchronize();   // wait for iou grid (all threads)

    ull k[8];
    #pragma unroll
    for (int rr = 0; rr < 8; rr++) {
        int n = w*256 + rr*32 + lane;
        ull key = 0ull;
        if (n < NN) {
            float v;
            float m = g_miou[b*NN + n];
            if (role == 0) {
                v = (m >= 0.5f) ? m : -1.0f;
            } else {
                bool neg = (m < 0.5f) && (g_cmax[b*NN + n] < 0.001f);
                v = neg ? m : -1.0f;
            }
            key = ((ull)float_ord(v) << 32) |
                  (unsigned int)(0xFFFFFFFFu - (unsigned int)n);
        }
        k[rr] = key;
    }
    warp_sort256_desc(k, lane);
    #pragma unroll
    for (int rr = 0; rr < 8; rr++) sA[w*256 + rr*32 + lane] = k[rr];
    __syncthreads();

    if (w < 4) {
        #pragma unroll
        for (int rr = 0; rr < 8; rr++) {
            int e = rr*32 + lane;
            k[rr] = umax64(sA[w*512 + e], sA[w*512 + 256 + (255 - e)]);
        }
        warp_merge256_desc(k, lane);
        #pragma unroll
        for (int rr = 0; rr < 8; rr++) sB[w*256 + rr*32 + lane] = k[rr];
    }
    __syncthreads();

    if (w < 2) {
        #pragma unroll
        for (int rr = 0; rr < 8; rr++) {
            int e = rr*32 + lane;
            k[rr] = umax64(sB[w*512 + e], sB[w*512 + 256 + (255 - e)]);
        }
        warp_merge256_desc(k, lane);
        #pragma unroll
        for (int rr = 0; rr < 8; rr++) sC[w*256 + rr*32 + lane] = k[rr];
    }
    __syncthreads();

    if (w == 0) {
        #pragma unroll
        for (int rr = 0; rr < 8; rr++) {
            int e = rr*32 + lane;
            k[rr] = umax64(sC[e], sC[256 + (255 - e)]);
        }
        warp_merge256_desc(k, lane);
        #pragma unroll
        for (int rr = 0; rr < 8; rr++) sF[rr*32 + lane] = k[rr];
    }
    __syncthreads();

    if (role == 0) {
        if (t < PP) {
            int i = t;
            int n = (int)(0xFFFFFFFFu - (unsigned int)sF[i]);
            float m = g_miou[b*NN + n];
            bool ok = (m >= 0.5f);
            int g = g_asn[b*NN + n];
            const float4 pb = ((const float4*)props)[b*NN + n];
            float q0 = pb.x, q1 = pb.y, q2 = pb.z, q3 = pb.w;
            int oT = b*TT + i;

            out[BASE_ROI + oT*4 + 0] = ok ? q0 : 0.0f;
            out[BASE_ROI + oT*4 + 1] = ok ? q1 : 0.0f;
            out[BASE_ROI + oT*4 + 2] = ok ? q2 : 0.0f;
            out[BASE_ROI + oT*4 + 3] = ok ? q3 : 0.0f;
            out[BASE_CLS + oT] = ok ? (float)cls[b*GG + g] : 0.0f;

            float d0=0.f, d1=0.f, d2=0.f, d3=0.f;
            if (ok) {
                float h  = q2 - q0, wd = q3 - q1;
                float cy = q0 + 0.5f*h, cx = q1 + 0.5f*wd;
                float gy1 = boxes[b*GG*4 + g*4+0], gx1 = boxes[b*GG*4 + g*4+1];
                float gy2 = boxes[b*GG*4 + g*4+2], gx2 = boxes[b*GG*4 + g*4+3];
                float gh = gy2 - gy1, gw = gx2 - gx1;
                float gcy = gy1 + 0.5f*gh, gcx = gx1 + 0.5f*gw;
                d0 = ((gcy - cy) / h) / 0.1f;
                d1 = ((gcx - cx) / wd) / 0.1f;
                d2 = logf(gh / h) / 0.2f;
                d3 = logf(gw / wd) / 0.2f;
            }
            out[BASE_DLT + oT*4 + 0] = d0;
            out[BASE_DLT + oT*4 + 1] = d1;
            out[BASE_DLT + oT*4 + 2] = d2;
            out[BASE_DLT + oT*4 + 3] = d3;

            int s = b*PP + i;
            g_sel_ok[s]      = ok ? 1 : 0;
            g_sel_gt[s]      = g;
            g_sel_box[s*4+0] = q0;
            g_sel_box[s*4+1] = q1;
            g_sel_box[s*4+2] = q2;
            g_sel_box[s*4+3] = q3;
        }
    } else {
        if (t < NEGN) {
            int i = t;
            int n = (int)(0xFFFFFFFFu - (unsigned int)sF[i]);
            float m = g_miou[b*NN + n];
            bool ok = (m < 0.5f) && (g_cmax[b*NN + n] < 0.001f);
            const float4 pb = ((const float4*)props)[b*NN + n];
            int oT = b*TT + PP + i;
            out[BASE_ROI + oT*4 + 0] = ok ? pb.x : 0.0f;
            out[BASE_ROI + oT*4 + 1] = ok ? pb.y : 0.0f;
            out[BASE_ROI + oT*4 + 2] = ok ? pb.z : 0.0f;
            out[BASE_ROI + oT*4 + 3] = ok ? pb.w : 0.0f;
            out[BASE_CLS + oT] = 0.0f;
            out[BASE_DLT + oT*4 + 0] = 0.0f;
            out[BASE_DLT + oT*4 + 1] = 0.0f;
            out[BASE_DLT + oT*4 + 2] = 0.0f;
            out[BASE_DLT + oT*4 + 3] = 0.0f;
        }
    }
}

// ---------------------------------------------------------------------------
// Kernel C: mask crop-resize. PDL secondary of select_kernel.
// TWO blocks per tile (392 px each) to spread scattered-load wavefronts over
// 2x the SMs/L1tex queues. Negative half-tiles: zeros, no dependency.
// VALIDATED bit-exact arithmetic — all rn intrinsics, no FMA contraction.
// ---------------------------------------------------------------------------
__device__ __forceinline__ float read_mask(const void* m, int mode, int b, int y, int x, int g) {
    size_t idx = (((size_t)b*HH + y)*WW + x)*GG + g;
    if (mode == 0) return ((const unsigned char*)m)[idx] ? 1.0f : 0.0f;
    if (mode == 1) return ((const float*)m)[idx];
    return (float)((const int*)m)[idx];
}

__global__ void __launch_bounds__(MPX) mask_kernel(const void* __restrict__ masks,
                                                   float* __restrict__ out)
{
    const int bt   = blockIdx.x >> 1;          // tile index
    const int half = blockIdx.x & 1;           // which half of the 784 px
    const int b = bt / TT, t = bt % TT;
    float* mout = out + BASE_MSK + (size_t)bt * (MH*MW);
    const int i = half * MPX + threadIdx.x;    // pixel index 0..783

    if (t >= PP) {                       // negatives: no dependency at all
        mout[i] = 0.0f;
        return;
    }

    cudaGridDependencySynchronize();     // wait for select grid (all threads)

    if (!g_sel_ok[b*PP + t]) {
        mout[i] = 0.0f;
        return;
    }
    const int s = b*PP + t;
    const int g = g_sel_gt[s];
    const float by1 = g_sel_box[s*4+0], bx1 = g_sel_box[s*4+1];
    const float by2 = g_sel_box[s*4+2], bx2 = g_sel_box[s*4+3];
    const int mode = g_mask_mode;

    const float dy = __fsub_rn(by2, by1);
    const float dx = __fsub_rn(bx2, bx1);
    const float baseY = __fmul_rn(by1, (float)(HH-1));
    const float baseX = __fmul_rn(bx1, (float)(WW-1));

    int py = i / MW, px = i % MW;
    float ty = __fdiv_rn((float)py, (float)(MH-1));
    float ys = __fadd_rn(baseY, __fmul_rn(__fmul_rn(ty, dy), (float)(HH-1)));
    float tx = __fdiv_rn((float)px, (float)(MW-1));
    float xs = __fadd_rn(baseX, __fmul_rn(__fmul_rn(tx, dx), (float)(WW-1)));

    float y0f = floorf(ys), x0f = floorf(xs);
    float wy = __fsub_rn(ys, y0f);
    float wx = __fsub_rn(xs, x0f);
    int y0 = min(max((int)y0f, 0), HH-1);
    int y1 = min(y0 + 1, HH-1);
    int x0 = min(max((int)x0f, 0), WW-1);
    int x1 = min(x0 + 1, WW-1);

    float v00 = read_mask(masks, mode, b, y0, x0, g);
    float v01 = read_mask(masks, mode, b, y0, x1, g);
    float v10 = read_mask(masks, mode, b, y1, x0, g);
    float v11 = read_mask(masks, mode, b, y1, x1, g);

    float omwx = __fsub_rn(1.0f, wx);
    float omwy = __fsub_rn(1.0f, wy);
    float top = __fadd_rn(__fmul_rn(v00, omwx), __fmul_rn(v01, wx));
    float bot = __fadd_rn(__fmul_rn(v10, omwx), __fmul_rn(v11, wx));
    float v   = __fadd_rn(__fmul_rn(top, omwy), __fmul_rn(bot, wy));
    mout[i] = rintf(v);   // jnp.round = half-to-even
}

// ---------------------------------------------------------------------------
extern "C" void kernel_launch(void* const* d_in, const int* in_sizes, int n_in,
                              void* d_out, int out_size)
{
    const float* props = (const float*)d_in[0];   // (B,N,4)
    const int*   cls   = (const int*)  d_in[1];   // (B,G)
    const float* boxes = (const float*)d_in[2];   // (B,G,4)
    const void*  masks = d_in[3];                 // (B,H,W,G)

    float* out = (float*)d_out;

    // K1: plain launch
    dim3 gridA(33, BB);
    iou_kernel<<<gridA, 256>>>(props, cls, boxes, masks);

    // K2: PDL secondary of K1
    {
        cudaLaunchConfig_t cfg = {};
        cfg.gridDim  = dim3(4, 1, 1);
        cfg.blockDim = dim3(256, 1, 1);
        cfg.stream   = 0;
        cudaLaunchAttribute a[1];
        a[0].id = cudaLaunchAttributeProgrammaticStreamSerialization;
        a[0].val.programmaticStreamSerializationAllowed = 1;
        cfg.attrs = a;
        cfg.numAttrs = 1;
        cudaLaunchKernelEx(&cfg, select_kernel, props, cls, boxes, out);
    }

    // K3: PDL secondary of K2 (2 blocks per tile; negative halves independent)
    {
        cudaLaunchConfig_t cfg = {};
        cfg.gridDim  = dim3(BB*TT*MSPLIT, 1, 1);
        cfg.blockDim = dim3(MPX, 1, 1);
        cfg.stream   = 0;
        cudaLaunchAttribute a[1];
        a[0].id = cudaLaunchAttributeProgrammaticStreamSerialization;
        a[0].val.programmaticStreamSerializationAllowed = 1;
        cfg.attrs = a;
        cfg.numAttrs = 1;
        cudaLaunchKernelEx(&cfg, mask_kernel, masks, out);
    }
}

// round 13
// speedup vs baseline: 1.3286x; 1.0013x over previous
#include <cuda_runtime.h>
#include <cstdint>
#include <math.h>

// Problem constants
#define BB   2
#define NN   2000
#define GG   100
#define HH   800
#define WW   800
#define TT   200
#define PP   66
#define NEGN 134
#define MH   28
#define MW   28

// d_out float32 layout (flattened tuple concat):
#define BASE_ROI 0
#define BASE_CLS (BB*TT*4)
#define BASE_DLT (BASE_CLS + BB*TT)
#define BASE_MSK (BASE_DLT + BB*TT*4)

// mask kernel split: 4 blocks per positive tile, 196 px each
#define MSPLIT 4
#define MPX    (MH*MW/MSPLIT)   // 196

typedef unsigned long long ull;

// Scratch (no device allocation allowed -> __device__ globals)
__device__ int   g_mask_mode;
__device__ int   g_sel_ok[BB*PP];
__device__ int   g_sel_gt[BB*PP];
__device__ float g_sel_box[BB*PP*4];
__device__ float g_miou[BB*NN];
__device__ float g_cmax[BB*NN];
__device__ int   g_asn [BB*NN];

__device__ __forceinline__ unsigned int float_ord(float f) {
    unsigned int u = __float_as_uint(f);
    return (u & 0x80000000u) ? ~u : (u | 0x80000000u);
}
__device__ __forceinline__ float ord_to_float(unsigned int k) {
    unsigned int u = (k & 0x80000000u) ? (k ^ 0x80000000u) : ~k;
    return __uint_as_float(u);
}
__device__ __forceinline__ ull umax64(ull a, ull b) { return a > b ? a : b; }
__device__ __forceinline__ ull umin64(ull a, ull b) { return a > b ? b : a; }

// ---------------------------------------------------------------------------
// Kernel A: IoU (4 lanes/proposal) + dtype detect + negative-mask zero-fill.
// PDL primary. grid = (33, BB): block (32,0) -> detect, (32,1) -> noop.
// The zero-fill for mask tiles t>=PP (statically negative) is grid-strided
// over the 64 iou blocks and overlaps the IoU compute.
// ---------------------------------------------------------------------------
__global__ void __launch_bounds__(256) iou_kernel(
    const float* __restrict__ props,   // (B,N,4)
    const int*   __restrict__ cls,     // (B,G)
    const float* __restrict__ boxes,   // (B,G,4)
    const void*  __restrict__ masks,
    float*       __restrict__ out)
{
    if (threadIdx.x == 0) cudaTriggerProgrammaticLaunchCompletion();

    if (blockIdx.x == 32) {
        if (blockIdx.y == 0 && threadIdx.x < 32) {
            const uint4* w4 = (const uint4*)masks;
            bool weird = false, sawF = false;
            for (int i = threadIdx.x; i < 512; i += 32) {   // 8KB sample
                uint4 v = w4[i];
                #define CHK(x) { unsigned int u = (x); \
                    if (u == 0x3F800000u) sawF = true; \
                    else if (u != 0u && u != 1u) weird = true; }
                CHK(v.x) CHK(v.y) CHK(v.z) CHK(v.w)
                #undef CHK
            }
            weird = __any_sync(0xFFFFFFFFu, weird);
            sawF  = __any_sync(0xFFFFFFFFu, sawF);
            if (threadIdx.x == 0) g_mask_mode = weird ? 0 : (sawF ? 1 : 2);
        }
        return;
    }

    const int b = blockIdx.y;
    const int t = threadIdx.x;

    // ---- negative-mask zero-fill (this image's span), float4 grid-stride ----
    {
        float4* span = (float4*)(out + BASE_MSK + (size_t)(b*TT + PP) * (MH*MW));
        const int nvec = (TT - PP) * (MH*MW) / 4;          // 26,264 float4s
        for (int i = blockIdx.x * 256 + t; i < nvec; i += 32 * 256)
            span[i] = make_float4(0.f, 0.f, 0.f, 0.f);
    }

    const int lane = t & 31;
    const int sub  = lane & 3;
    const int n    = blockIdx.x * 64 + (t >> 2);

    __shared__ float4 s_gt[GG];
    __shared__ int    s_cls[GG];
    if (t < GG)                   s_gt[t]      = ((const float4*)boxes)[b*GG + t];
    if (t >= 128 && t < 128 + GG) s_cls[t-128] = cls[b*GG + (t-128)];
    __syncthreads();

    if (n >= NN) return;

    const float4 pb = ((const float4*)props)[b*NN + n];
    const float py1 = pb.x, px1 = pb.y, py2 = pb.z, px2 = pb.w;
    const float a1 = (py2 - py1) * (px2 - px1);

    ull bestkey = 0ull;
    float cmax = -1.0f;
    #pragma unroll
    for (int g = sub; g < GG; g += 4) {        // 25 iterations
        float4 gb = s_gt[g];
        float yy1 = fmaxf(py1, gb.x), xx1 = fmaxf(px1, gb.y);
        float yy2 = fminf(py2, gb.z), xx2 = fminf(px2, gb.w);
        float ih = fmaxf(yy2 - yy1, 0.0f);
        float iw = fmaxf(xx2 - xx1, 0.0f);
        float inter = ih * iw;
        float a2 = (gb.z - gb.x) * (gb.w - gb.y);
        float uni = a1 + a2 - inter;
        float iou = inter / fmaxf(uni, 1e-12f);
        bool crowd = (s_cls[g] < 0);
        float ov = crowd ? -1.0f : iou;
        ull key = ((ull)float_ord(ov) << 32) |
                  (unsigned int)(0xFFFFFFFFu - (unsigned int)g);
        bestkey = umax64(bestkey, key);
        cmax = fmaxf(cmax, crowd ? iou : -1.0f);
    }
    bestkey = umax64(bestkey, __shfl_xor_sync(0xFFFFFFFFu, bestkey, 1));
    cmax    = fmaxf(cmax,     __shfl_xor_sync(0xFFFFFFFFu, cmax,    1));
    bestkey = umax64(bestkey, __shfl_xor_sync(0xFFFFFFFFu, bestkey, 2));
    cmax    = fmaxf(cmax,     __shfl_xor_sync(0xFFFFFFFFu, cmax,    2));

    if (sub == 0) {
        g_miou[b*NN + n] = ord_to_float((unsigned int)(bestkey >> 32));
        g_asn [b*NN + n] = (int)(0xFFFFFFFFu - (unsigned int)(bestkey & 0xFFFFFFFFull));
        g_cmax[b*NN + n] = cmax;
    }
}

// ---------------------------------------------------------------------------
// In-warp bitonic sort of 256 u64 keys (k[8]/lane, elem = rr*32+lane), DESC.
// ---------------------------------------------------------------------------
__device__ __forceinline__ void cas_pair(ull& a, ull& b, bool desc) {
    ull hi = umax64(a, b), lo = umin64(a, b);
    a = desc ? hi : lo;  b = desc ? lo : hi;
}

__device__ __forceinline__ void warp_sort256_desc(ull k[8], int lane) {
    #pragma unroll
    for (int kk = 2; kk <= 256; kk <<= 1) {
        #pragma unroll
        for (int j = kk >> 1; j >= 32; j >>= 1) {
            const int rj = j >> 5;
            #pragma unroll
            for (int rr = 0; rr < 8; rr++) if ((rr & rj) == 0) {
                bool desc = (((rr*32) & kk) == 0);
                cas_pair(k[rr], k[rr | rj], desc);
            }
        }
        #pragma unroll
        for (int j = (kk >> 1) < 32 ? (kk >> 1) : 16; j >= 1; j >>= 1) {
            #pragma unroll
            for (int rr = 0; rr < 8; rr++) {
                ull p = __shfl_xor_sync(0xFFFFFFFFu, k[rr], j);
                bool desc = (((rr*32 + lane) & kk) == 0);
                bool up = ((lane & j) == 0);
                k[rr] = (up == desc) ? umax64(k[rr], p) : umin64(k[rr], p);
            }
        }
    }
}

__device__ __forceinline__ void warp_merge256_desc(ull k[8], int lane) {
    #pragma unroll
    for (int j = 128; j >= 32; j >>= 1) {
        const int rj = j >> 5;
        #pragma unroll
        for (int rr = 0; rr < 8; rr++) if ((rr & rj) == 0)
            cas_pair(k[rr], k[rr | rj], true);
    }
    #pragma unroll
    for (int j = 16; j >= 1; j >>= 1) {
        #pragma unroll
        for (int rr = 0; rr < 8; rr++) {
            ull p = __shfl_xor_sync(0xFFFFFFFFu, k[rr], j);
            bool up = ((lane & j) == 0);
            k[rr] = up ? umax64(k[rr], p) : umin64(k[rr], p);
        }
    }
}

// ---------------------------------------------------------------------------
// Kernel B: top-k select + output writes. PDL secondary of iou_kernel.
// ---------------------------------------------------------------------------
__global__ void __launch_bounds__(256) select_kernel(
    const float* __restrict__ props,
    const int*   __restrict__ cls,
    const float* __restrict__ boxes,
    float*       __restrict__ out)
{
    if (threadIdx.x == 0) cudaTriggerProgrammaticLaunchCompletion();

    const int b    = blockIdx.x >> 1;
    const int role = blockIdx.x & 1;          // 0 = positives, 1 = negatives
    const int t    = threadIdx.x;
    const int lane = t & 31, w = t >> 5;

    __shared__ ull sA[2048];
    __shared__ ull sB[1024];
    __shared__ ull sC[512];
    __shared__ ull sF[256];

    cudaGridDependencySynchronize();   // wait for iou grid (all threads)

    ull k[8];
    #pragma unroll
    for (int rr = 0; rr < 8; rr++) {
        int n = w*256 + rr*32 + lane;
        ull key = 0ull;
        if (n < NN) {
            float v;
            float m = g_miou[b*NN + n];
            if (role == 0) {
                v = (m >= 0.5f) ? m : -1.0f;
            } else {
                bool neg = (m < 0.5f) && (g_cmax[b*NN + n] < 0.001f);
                v = neg ? m : -1.0f;
            }
            key = ((ull)float_ord(v) << 32) |
                  (unsigned int)(0xFFFFFFFFu - (unsigned int)n);
        }
        k[rr] = key;
    }
    warp_sort256_desc(k, lane);
    #pragma unroll
    for (int rr = 0; rr < 8; rr++) sA[w*256 + rr*32 + lane] = k[rr];
    __syncthreads();

    if (w < 4) {
        #pragma unroll
        for (int rr = 0; rr < 8; rr++) {
            int e = rr*32 + lane;
            k[rr] = umax64(sA[w*512 + e], sA[w*512 + 256 + (255 - e)]);
        }
        warp_merge256_desc(k, lane);
        #pragma unroll
        for (int rr = 0; rr < 8; rr++) sB[w*256 + rr*32 + lane] = k[rr];
    }
    __syncthreads();

    if (w < 2) {
        #pragma unroll
        for (int rr = 0; rr < 8; rr++) {
            int e = rr*32 + lane;
            k[rr] = umax64(sB[w*512 + e], sB[w*512 + 256 + (255 - e)]);
        }
        warp_merge256_desc(k, lane);
        #pragma unroll
        for (int rr = 0; rr < 8; rr++) sC[w*256 + rr*32 + lane] = k[rr];
    }
    __syncthreads();

    if (w == 0) {
        #pragma unroll
        for (int rr = 0; rr < 8; rr++) {
            int e = rr*32 + lane;
            k[rr] = umax64(sC[e], sC[256 + (255 - e)]);
        }
        warp_merge256_desc(k, lane);
        #pragma unroll
        for (int rr = 0; rr < 8; rr++) sF[rr*32 + lane] = k[rr];
    }
    __syncthreads();

    if (role == 0) {
        if (t < PP) {
            int i = t;
            int n = (int)(0xFFFFFFFFu - (unsigned int)sF[i]);
            float m = g_miou[b*NN + n];
            bool ok = (m >= 0.5f);
            int g = g_asn[b*NN + n];
            const float4 pb = ((const float4*)props)[b*NN + n];
            float q0 = pb.x, q1 = pb.y, q2 = pb.z, q3 = pb.w;
            int oT = b*TT + i;

            out[BASE_ROI + oT*4 + 0] = ok ? q0 : 0.0f;
            out[BASE_ROI + oT*4 + 1] = ok ? q1 : 0.0f;
            out[BASE_ROI + oT*4 + 2] = ok ? q2 : 0.0f;
            out[BASE_ROI + oT*4 + 3] = ok ? q3 : 0.0f;
            out[BASE_CLS + oT] = ok ? (float)cls[b*GG + g] : 0.0f;

            float d0=0.f, d1=0.f, d2=0.f, d3=0.f;
            if (ok) {
                float h  = q2 - q0, wd = q3 - q1;
                float cy = q0 + 0.5f*h, cx = q1 + 0.5f*wd;
                float gy1 = boxes[b*GG*4 + g*4+0], gx1 = boxes[b*GG*4 + g*4+1];
                float gy2 = boxes[b*GG*4 + g*4+2], gx2 = boxes[b*GG*4 + g*4+3];
                float gh = gy2 - gy1, gw = gx2 - gx1;
                float gcy = gy1 + 0.5f*gh, gcx = gx1 + 0.5f*gw;
                d0 = ((gcy - cy) / h) / 0.1f;
                d1 = ((gcx - cx) / wd) / 0.1f;
                d2 = logf(gh / h) / 0.2f;
                d3 = logf(gw / wd) / 0.2f;
            }
            out[BASE_DLT + oT*4 + 0] = d0;
            out[BASE_DLT + oT*4 + 1] = d1;
            out[BASE_DLT + oT*4 + 2] = d2;
            out[BASE_DLT + oT*4 + 3] = d3;

            int s = b*PP + i;
            g_sel_ok[s]      = ok ? 1 : 0;
            g_sel_gt[s]      = g;
            g_sel_box[s*4+0] = q0;
            g_sel_box[s*4+1] = q1;
            g_sel_box[s*4+2] = q2;
            g_sel_box[s*4+3] = q3;
        }
    } else {
        if (t < NEGN) {
            int i = t;
            int n = (int)(0xFFFFFFFFu - (unsigned int)sF[i]);
            float m = g_miou[b*NN + n];
            bool ok = (m < 0.5f) && (g_cmax[b*NN + n] < 0.001f);
            const float4 pb = ((const float4*)props)[b*NN + n];
            int oT = b*TT + PP + i;
            out[BASE_ROI + oT*4 + 0] = ok ? pb.x : 0.0f;
            out[BASE_ROI + oT*4 + 1] = ok ? pb.y : 0.0f;
            out[BASE_ROI + oT*4 + 2] = ok ? pb.z : 0.0f;
            out[BASE_ROI + oT*4 + 3] = ok ? pb.w : 0.0f;
            out[BASE_CLS + oT] = 0.0f;
            out[BASE_DLT + oT*4 + 0] = 0.0f;
            out[BASE_DLT + oT*4 + 1] = 0.0f;
            out[BASE_DLT + oT*4 + 2] = 0.0f;
            out[BASE_DLT + oT*4 + 3] = 0.0f;
        }
    }
}

// ---------------------------------------------------------------------------
// Kernel C: mask crop-resize for POSITIVE tiles only (negatives zero-filled
// by iou_kernel). PDL secondary of select_kernel. 4 blocks per tile, 196 px.
// VALIDATED bit-exact arithmetic — all rn intrinsics, no FMA contraction.
// ---------------------------------------------------------------------------
__device__ __forceinline__ float read_mask(const void* m, int mode, int b, int y, int x, int g) {
    size_t idx = (((size_t)b*HH + y)*WW + x)*GG + g;
    if (mode == 0) return ((const unsigned char*)m)[idx] ? 1.0f : 0.0f;
    if (mode == 1) return ((const float*)m)[idx];
    return (float)((const int*)m)[idx];
}

__global__ void __launch_bounds__(MPX) mask_kernel(const void* __restrict__ masks,
                                                   float* __restrict__ out)
{
    const int pt   = blockIdx.x >> 2;          // positive-tile index 0..BB*PP-1
    const int quad = blockIdx.x & 3;
    const int b = pt / PP, t = pt % PP;
    float* mout = out + BASE_MSK + (size_t)(b*TT + t) * (MH*MW);
    const int i = quad * MPX + threadIdx.x;    // pixel index 0..783

    cudaGridDependencySynchronize();           // wait for select grid

    if (!g_sel_ok[b*PP + t]) {
        mout[i] = 0.0f;
        return;
    }
    const int s = b*PP + t;
    const int g = g_sel_gt[s];
    const float by1 = g_sel_box[s*4+0], bx1 = g_sel_box[s*4+1];
    const float by2 = g_sel_box[s*4+2], bx2 = g_sel_box[s*4+3];
    const int mode = g_mask_mode;

    const float dy = __fsub_rn(by2, by1);
    const float dx = __fsub_rn(bx2, bx1);
    const float baseY = __fmul_rn(by1, (float)(HH-1));
    const float baseX = __fmul_rn(bx1, (float)(WW-1));

    int py = i / MW, px = i % MW;
    float ty = __fdiv_rn((float)py, (float)(MH-1));
    float ys = __fadd_rn(baseY, __fmul_rn(__fmul_rn(ty, dy), (float)(HH-1)));
    float tx = __fdiv_rn((float)px, (float)(MW-1));
    float xs = __fadd_rn(baseX, __fmul_rn(__fmul_rn(tx, dx), (float)(WW-1)));

    float y0f = floorf(ys), x0f = floorf(xs);
    float wy = __fsub_rn(ys, y0f);
    float wx = __fsub_rn(xs, x0f);
    int y0 = min(max((int)y0f, 0), HH-1);
    int y1 = min(y0 + 1, HH-1);
    int x0 = min(max((int)x0f, 0), WW-1);
    int x1 = min(x0 + 1, WW-1);

    float v00 = read_mask(masks, mode, b, y0, x0, g);
    float v01 = read_mask(masks, mode, b, y0, x1, g);
    float v10 = read_mask(masks, mode, b, y1, x0, g);
    float v11 = read_mask(masks, mode, b, y1, x1, g);

    float omwx = __fsub_rn(1.0f, wx);
    float omwy = __fsub_rn(1.0f, wy);
    float top = __fadd_rn(__fmul_rn(v00, omwx), __fmul_rn(v01, wx));
    float bot = __fadd_rn(__fmul_rn(v10, omwx), __fmul_rn(v11, wx));
    float v   = __fadd_rn(__fmul_rn(top, omwy), __fmul_rn(bot, wy));
    mout[i] = rintf(v);   // jnp.round = half-to-even
}

// ---------------------------------------------------------------------------
extern "C" void kernel_launch(void* const* d_in, const int* in_sizes, int n_in,
                              void* d_out, int out_size)
{
    const float* props = (const float*)d_in[0];   // (B,N,4)
    const int*   cls   = (const int*)  d_in[1];   // (B,G)
    const float* boxes = (const float*)d_in[2];   // (B,G,4)
    const void*  masks = d_in[3];                 // (B,H,W,G)

    float* out = (float*)d_out;

    // K1: plain launch (iou + detect + negative zero-fill)
    dim3 gridA(33, BB);
    iou_kernel<<<gridA, 256>>>(props, cls, boxes, masks, out);

    // K2: PDL secondary of K1
    {
        cudaLaunchConfig_t cfg = {};
        cfg.gridDim  = dim3(4, 1, 1);
        cfg.blockDim = dim3(256, 1, 1);
        cfg.stream   = 0;
        cudaLaunchAttribute a[1];
        a[0].id = cudaLaunchAttributeProgrammaticStreamSerialization;
        a[0].val.programmaticStreamSerializationAllowed = 1;
        cfg.attrs = a;
        cfg.numAttrs = 1;
        cudaLaunchKernelEx(&cfg, select_kernel, props, cls, boxes, out);
    }

    // K3: PDL secondary of K2 — positive tiles only, 4 blocks each
    {
        cudaLaunchConfig_t cfg = {};
        cfg.gridDim  = dim3(BB*PP*MSPLIT, 1, 1);
        cfg.blockDim = dim3(MPX, 1, 1);
        cfg.stream   = 0;
        cudaLaunchAttribute a[1];
        a[0].id = cudaLaunchAttributeProgrammaticStreamSerialization;
        a[0].val.programmaticStreamSerializationAllowed = 1;
        cfg.attrs = a;
        cfg.numAttrs = 1;
        cudaLaunchKernelEx(&cfg, mask_kernel, masks, out);
    }
}

// round 14
// speedup vs baseline: 1.3599x; 1.0236x over previous
#include <cuda_runtime.h>
#include <cstdint>
#include <math.h>

// Problem constants
#define BB   2
#define NN   2000
#define GG   100
#define HH   800
#define WW   800
#define TT   200
#define PP   66
#define NEGN 134
#define MH   28
#define MW   28

// d_out float32 layout (flattened tuple concat):
#define BASE_ROI 0
#define BASE_CLS (BB*TT*4)
#define BASE_DLT (BASE_CLS + BB*TT)
#define BASE_MSK (BASE_DLT + BB*TT*4)

// mask kernel split: 4 blocks per positive tile, 196 px each
#define MSPLIT 4
#define MPX    (MH*MW/MSPLIT)   // 196

typedef unsigned long long ull;

// Scratch (no device allocation allowed -> __device__ globals)
__device__ int   g_mask_mode;
__device__ int   g_sel_ok[BB*PP];
__device__ int   g_sel_gt[BB*PP];
__device__ float g_sel_box[BB*PP*4];
__device__ float g_miou[BB*NN];
__device__ float g_cmax[BB*NN];
__device__ int   g_asn [BB*NN];

__device__ __forceinline__ unsigned int float_ord(float f) {
    unsigned int u = __float_as_uint(f);
    return (u & 0x80000000u) ? ~u : (u | 0x80000000u);
}
__device__ __forceinline__ float ord_to_float(unsigned int k) {
    unsigned int u = (k & 0x80000000u) ? (k ^ 0x80000000u) : ~k;
    return __uint_as_float(u);
}
__device__ __forceinline__ ull umax64(ull a, ull b) { return a > b ? a : b; }
__device__ __forceinline__ ull umin64(ull a, ull b) { return a > b ? b : a; }

// ---------------------------------------------------------------------------
// Kernel A: IoU (8 lanes/proposal -> 13-iter chain) + dtype detect +
// negative-mask zero-fill. PDL primary.
//   grid = (65, BB): blocks 0..63 iou (32 proposals each), block (64,0) detect.
// ---------------------------------------------------------------------------
__global__ void __launch_bounds__(256) iou_kernel(
    const float* __restrict__ props,   // (B,N,4)
    const int*   __restrict__ cls,     // (B,G)
    const float* __restrict__ boxes,   // (B,G,4)
    const void*  __restrict__ masks,
    float*       __restrict__ out)
{
    if (threadIdx.x == 0) cudaTriggerProgrammaticLaunchCompletion();

    if (blockIdx.x == 64) {
        if (blockIdx.y == 0 && threadIdx.x < 32) {
            const uint4* w4 = (const uint4*)masks;
            bool weird = false, sawF = false;
            for (int i = threadIdx.x; i < 512; i += 32) {   // 8KB sample
                uint4 v = w4[i];
                #define CHK(x) { unsigned int u = (x); \
                    if (u == 0x3F800000u) sawF = true; \
                    else if (u != 0u && u != 1u) weird = true; }
                CHK(v.x) CHK(v.y) CHK(v.z) CHK(v.w)
                #undef CHK
            }
            weird = __any_sync(0xFFFFFFFFu, weird);
            sawF  = __any_sync(0xFFFFFFFFu, sawF);
            if (threadIdx.x == 0) g_mask_mode = weird ? 0 : (sawF ? 1 : 2);
        }
        return;
    }

    const int b = blockIdx.y;
    const int t = threadIdx.x;
    const int lane = t & 31;
    const int sub  = lane & 7;                  // 8-lane GT slice
    const int n    = blockIdx.x * 32 + (t >> 3);    // 64*32 = 2048 >= 2000

    // Prefetch proposal early (overlaps smem staging)
    float4 pb = make_float4(0.f, 0.f, 0.f, 0.f);
    if (n < NN) pb = ((const float4*)props)[b*NN + n];

    // ---- negative-mask zero-fill (this image's span), float4 grid-stride ----
    {
        float4* span = (float4*)(out + BASE_MSK + (size_t)(b*TT + PP) * (MH*MW));
        const int nvec = (TT - PP) * (MH*MW) / 4;          // 26,264 float4s
        for (int i = blockIdx.x * 256 + t; i < nvec; i += 64 * 256)
            span[i] = make_float4(0.f, 0.f, 0.f, 0.f);
    }

    __shared__ float4 s_gt[GG];
    __shared__ int    s_cls[GG];
    if (t < GG)                   s_gt[t]      = ((const float4*)boxes)[b*GG + t];
    if (t >= 128 && t < 128 + GG) s_cls[t-128] = cls[b*GG + (t-128)];
    __syncthreads();

    if (n >= NN) return;

    const float py1 = pb.x, px1 = pb.y, py2 = pb.z, px2 = pb.w;
    const float a1 = (py2 - py1) * (px2 - px1);

    ull bestkey = 0ull;
    float cmax = -1.0f;
    #pragma unroll
    for (int g = sub; g < GG; g += 8) {        // 13 iterations (12 for sub>=4)
        float4 gb = s_gt[g];
        float yy1 = fmaxf(py1, gb.x), xx1 = fmaxf(px1, gb.y);
        float yy2 = fminf(py2, gb.z), xx2 = fminf(px2, gb.w);
        float ih = fmaxf(yy2 - yy1, 0.0f);
        float iw = fmaxf(xx2 - xx1, 0.0f);
        float inter = ih * iw;
        float a2 = (gb.z - gb.x) * (gb.w - gb.y);
        float uni = a1 + a2 - inter;
        float iou = inter / fmaxf(uni, 1e-12f);
        bool crowd = (s_cls[g] < 0);
        float ov = crowd ? -1.0f : iou;
        ull key = ((ull)float_ord(ov) << 32) |
                  (unsigned int)(0xFFFFFFFFu - (unsigned int)g);
        bestkey = umax64(bestkey, key);
        cmax = fmaxf(cmax, crowd ? iou : -1.0f);
    }
    // reduce across the 8 sub-lanes (offsets 1, 2, 4)
    bestkey = umax64(bestkey, __shfl_xor_sync(0xFFFFFFFFu, bestkey, 1));
    cmax    = fmaxf(cmax,     __shfl_xor_sync(0xFFFFFFFFu, cmax,    1));
    bestkey = umax64(bestkey, __shfl_xor_sync(0xFFFFFFFFu, bestkey, 2));
    cmax    = fmaxf(cmax,     __shfl_xor_sync(0xFFFFFFFFu, cmax,    2));
    bestkey = umax64(bestkey, __shfl_xor_sync(0xFFFFFFFFu, bestkey, 4));
    cmax    = fmaxf(cmax,     __shfl_xor_sync(0xFFFFFFFFu, cmax,    4));

    if (sub == 0) {
        g_miou[b*NN + n] = ord_to_float((unsigned int)(bestkey >> 32));
        g_asn [b*NN + n] = (int)(0xFFFFFFFFu - (unsigned int)(bestkey & 0xFFFFFFFFull));
        g_cmax[b*NN + n] = cmax;
    }
}

// ---------------------------------------------------------------------------
// In-warp bitonic sort of 256 u64 keys (k[8]/lane, elem = rr*32+lane), DESC.
// ---------------------------------------------------------------------------
__device__ __forceinline__ void cas_pair(ull& a, ull& b, bool desc) {
    ull hi = umax64(a, b), lo = umin64(a, b);
    a = desc ? hi : lo;  b = desc ? lo : hi;
}

__device__ __forceinline__ void warp_sort256_desc(ull k[8], int lane) {
    #pragma unroll
    for (int kk = 2; kk <= 256; kk <<= 1) {
        #pragma unroll
        for (int j = kk >> 1; j >= 32; j >>= 1) {
            const int rj = j >> 5;
            #pragma unroll
            for (int rr = 0; rr < 8; rr++) if ((rr & rj) == 0) {
                bool desc = (((rr*32) & kk) == 0);
                cas_pair(k[rr], k[rr | rj], desc);
            }
        }
        #pragma unroll
        for (int j = (kk >> 1) < 32 ? (kk >> 1) : 16; j >= 1; j >>= 1) {
            #pragma unroll
            for (int rr = 0; rr < 8; rr++) {
                ull p = __shfl_xor_sync(0xFFFFFFFFu, k[rr], j);
                bool desc = (((rr*32 + lane) & kk) == 0);
                bool up = ((lane & j) == 0);
                k[rr] = (up == desc) ? umax64(k[rr], p) : umin64(k[rr], p);
            }
        }
    }
}

__device__ __forceinline__ void warp_merge256_desc(ull k[8], int lane) {
    #pragma unroll
    for (int j = 128; j >= 32; j >>= 1) {
        const int rj = j >> 5;
        #pragma unroll
        for (int rr = 0; rr < 8; rr++) if ((rr & rj) == 0)
            cas_pair(k[rr], k[rr | rj], true);
    }
    #pragma unroll
    for (int j = 16; j >= 1; j >>= 1) {
        #pragma unroll
        for (int rr = 0; rr < 8; rr++) {
            ull p = __shfl_xor_sync(0xFFFFFFFFu, k[rr], j);
            bool up = ((lane & j) == 0);
            k[rr] = up ? umax64(k[rr], p) : umin64(k[rr], p);
        }
    }
}

// ---------------------------------------------------------------------------
// Kernel B: top-k select + output writes. PDL secondary of iou_kernel.
// ---------------------------------------------------------------------------
__global__ void __launch_bounds__(256) select_kernel(
    const float* __restrict__ props,
    const int*   __restrict__ cls,
    const float* __restrict__ boxes,
    float*       __restrict__ out)
{
    if (threadIdx.x == 0) cudaTriggerProgrammaticLaunchCompletion();

    const int b    = blockIdx.x >> 1;
    const int role = blockIdx.x & 1;          // 0 = positives, 1 = negatives
    const int t    = threadIdx.x;
    const int lane = t & 31, w = t >> 5;

    __shared__ ull sA[2048];
    __shared__ ull sB[1024];
    __shared__ ull sC[512];
    __shared__ ull sF[256];

    cudaGridDependencySynchronize();   // wait for iou grid (all threads)

    ull k[8];
    #pragma unroll
    for (int rr = 0; rr < 8; rr++) {
        int n = w*256 + rr*32 + lane;
        ull key = 0ull;
        if (n < NN) {
            float v;
            float m = g_miou[b*NN + n];
            if (role == 0) {
                v = (m >= 0.5f) ? m : -1.0f;
            } else {
                bool neg = (m < 0.5f) && (g_cmax[b*NN + n] < 0.001f);
                v = neg ? m : -1.0f;
            }
            key = ((ull)float_ord(v) << 32) |
                  (unsigned int)(0xFFFFFFFFu - (unsigned int)n);
        }
        k[rr] = key;
    }
    warp_sort256_desc(k, lane);
    #pragma unroll
    for (int rr = 0; rr < 8; rr++) sA[w*256 + rr*32 + lane] = k[rr];
    __syncthreads();

    if (w < 4) {
        #pragma unroll
        for (int rr = 0; rr < 8; rr++) {
            int e = rr*32 + lane;
            k[rr] = umax64(sA[w*512 + e], sA[w*512 + 256 + (255 - e)]);
        }
        warp_merge256_desc(k, lane);
        #pragma unroll
        for (int rr = 0; rr < 8; rr++) sB[w*256 + rr*32 + lane] = k[rr];
    }
    __syncthreads();

    if (w < 2) {
        #pragma unroll
        for (int rr = 0; rr < 8; rr++) {
            int e = rr*32 + lane;
            k[rr] = umax64(sB[w*512 + e], sB[w*512 + 256 + (255 - e)]);
        }
        warp_merge256_desc(k, lane);
        #pragma unroll
        for (int rr = 0; rr < 8; rr++) sC[w*256 + rr*32 + lane] = k[rr];
    }
    __syncthreads();

    if (w == 0) {
        #pragma unroll
        for (int rr = 0; rr < 8; rr++) {
            int e = rr*32 + lane;
            k[rr] = umax64(sC[e], sC[256 + (255 - e)]);
        }
        warp_merge256_desc(k, lane);
        #pragma unroll
        for (int rr = 0; rr < 8; rr++) sF[rr*32 + lane] = k[rr];
    }
    __syncthreads();

    if (role == 0) {
        if (t < PP) {
            int i = t;
            int n = (int)(0xFFFFFFFFu - (unsigned int)sF[i]);
            float m = g_miou[b*NN + n];
            bool ok = (m >= 0.5f);
            int g = g_asn[b*NN + n];
            const float4 pb = ((const float4*)props)[b*NN + n];
            float q0 = pb.x, q1 = pb.y, q2 = pb.z, q3 = pb.w;
            int oT = b*TT + i;

            out[BASE_ROI + oT*4 + 0] = ok ? q0 : 0.0f;
            out[BASE_ROI + oT*4 + 1] = ok ? q1 : 0.0f;
            out[BASE_ROI + oT*4 + 2] = ok ? q2 : 0.0f;
            out[BASE_ROI + oT*4 + 3] = ok ? q3 : 0.0f;
            out[BASE_CLS + oT] = ok ? (float)cls[b*GG + g] : 0.0f;

            float d0=0.f, d1=0.f, d2=0.f, d3=0.f;
            if (ok) {
                float h  = q2 - q0, wd = q3 - q1;
                float cy = q0 + 0.5f*h, cx = q1 + 0.5f*wd;
                float gy1 = boxes[b*GG*4 + g*4+0], gx1 = boxes[b*GG*4 + g*4+1];
                float gy2 = boxes[b*GG*4 + g*4+2], gx2 = boxes[b*GG*4 + g*4+3];
                float gh = gy2 - gy1, gw = gx2 - gx1;
                float gcy = gy1 + 0.5f*gh, gcx = gx1 + 0.5f*gw;
                d0 = ((gcy - cy) / h) / 0.1f;
                d1 = ((gcx - cx) / wd) / 0.1f;
                d2 = logf(gh / h) / 0.2f;
                d3 = logf(gw / wd) / 0.2f;
            }
            out[BASE_DLT + oT*4 + 0] = d0;
            out[BASE_DLT + oT*4 + 1] = d1;
            out[BASE_DLT + oT*4 + 2] = d2;
            out[BASE_DLT + oT*4 + 3] = d3;

            int s = b*PP + i;
            g_sel_ok[s]      = ok ? 1 : 0;
            g_sel_gt[s]      = g;
            g_sel_box[s*4+0] = q0;
            g_sel_box[s*4+1] = q1;
            g_sel_box[s*4+2] = q2;
            g_sel_box[s*4+3] = q3;
        }
    } else {
        if (t < NEGN) {
            int i = t;
            int n = (int)(0xFFFFFFFFu - (unsigned int)sF[i]);
            float m = g_miou[b*NN + n];
            bool ok = (m < 0.5f) && (g_cmax[b*NN + n] < 0.001f);
            const float4 pb = ((const float4*)props)[b*NN + n];
            int oT = b*TT + PP + i;
            out[BASE_ROI + oT*4 + 0] = ok ? pb.x : 0.0f;
            out[BASE_ROI + oT*4 + 1] = ok ? pb.y : 0.0f;
            out[BASE_ROI + oT*4 + 2] = ok ? pb.z : 0.0f;
            out[BASE_ROI + oT*4 + 3] = ok ? pb.w : 0.0f;
            out[BASE_CLS + oT] = 0.0f;
            out[BASE_DLT + oT*4 + 0] = 0.0f;
            out[BASE_DLT + oT*4 + 1] = 0.0f;
            out[BASE_DLT + oT*4 + 2] = 0.0f;
            out[BASE_DLT + oT*4 + 3] = 0.0f;
        }
    }
}

// ---------------------------------------------------------------------------
// Kernel C: mask crop-resize for POSITIVE tiles only (negatives zero-filled
// by iou_kernel). PDL secondary of select_kernel. 4 blocks per tile, 196 px.
// VALIDATED bit-exact arithmetic — all rn intrinsics, no FMA contraction.
// ---------------------------------------------------------------------------
__device__ __forceinline__ float read_mask(const void* m, int mode, int b, int y, int x, int g) {
    size_t idx = (((size_t)b*HH + y)*WW + x)*GG + g;
    if (mode == 0) return ((const unsigned char*)m)[idx] ? 1.0f : 0.0f;
    if (mode == 1) return ((const float*)m)[idx];
    return (float)((const int*)m)[idx];
}

__global__ void __launch_bounds__(MPX) mask_kernel(const void* __restrict__ masks,
                                                   float* __restrict__ out)
{
    const int pt   = blockIdx.x >> 2;          // positive-tile index 0..BB*PP-1
    const int quad = blockIdx.x & 3;
    const int b = pt / PP, t = pt % PP;
    float* mout = out + BASE_MSK + (size_t)(b*TT + t) * (MH*MW);
    const int i = quad * MPX + threadIdx.x;    // pixel index 0..783

    cudaGridDependencySynchronize();           // wait for select grid

    if (!g_sel_ok[b*PP + t]) {
        mout[i] = 0.0f;
        return;
    }
    const int s = b*PP + t;
    const int g = g_sel_gt[s];
    const float by1 = g_sel_box[s*4+0], bx1 = g_sel_box[s*4+1];
    const float by2 = g_sel_box[s*4+2], bx2 = g_sel_box[s*4+3];
    const int mode = g_mask_mode;

    const float dy = __fsub_rn(by2, by1);
    const float dx = __fsub_rn(bx2, bx1);
    const float baseY = __fmul_rn(by1, (float)(HH-1));
    const float baseX = __fmul_rn(bx1, (float)(WW-1));

    int py = i / MW, px = i % MW;
    float ty = __fdiv_rn((float)py, (float)(MH-1));
    float ys = __fadd_rn(baseY, __fmul_rn(__fmul_rn(ty, dy), (float)(HH-1)));
    float tx = __fdiv_rn((float)px, (float)(MW-1));
    float xs = __fadd_rn(baseX, __fmul_rn(__fmul_rn(tx, dx), (float)(WW-1)));

    float y0f = floorf(ys), x0f = floorf(xs);
    float wy = __fsub_rn(ys, y0f);
    float wx = __fsub_rn(xs, x0f);
    int y0 = min(max((int)y0f, 0), HH-1);
    int y1 = min(y0 + 1, HH-1);
    int x0 = min(max((int)x0f, 0), WW-1);
    int x1 = min(x0 + 1, WW-1);

    float v00 = read_mask(masks, mode, b, y0, x0, g);
    float v01 = read_mask(masks, mode, b, y0, x1, g);
    float v10 = read_mask(masks, mode, b, y1, x0, g);
    float v11 = read_mask(masks, mode, b, y1, x1, g);

    float omwx = __fsub_rn(1.0f, wx);
    float omwy = __fsub_rn(1.0f, wy);
    float top = __fadd_rn(__fmul_rn(v00, omwx), __fmul_rn(v01, wx));
    float bot = __fadd_rn(__fmul_rn(v10, omwx), __fmul_rn(v11, wx));
    float v   = __fadd_rn(__fmul_rn(top, omwy), __fmul_rn(bot, wy));
    mout[i] = rintf(v);   // jnp.round = half-to-even
}

// ---------------------------------------------------------------------------
extern "C" void kernel_launch(void* const* d_in, const int* in_sizes, int n_in,
                              void* d_out, int out_size)
{
    const float* props = (const float*)d_in[0];   // (B,N,4)
    const int*   cls   = (const int*)  d_in[1];   // (B,G)
    const float* boxes = (const float*)d_in[2];   // (B,G,4)
    const void*  masks = d_in[3];                 // (B,H,W,G)

    float* out = (float*)d_out;

    // K1: plain launch (iou + detect + negative zero-fill)
    dim3 gridA(65, BB);
    iou_kernel<<<gridA, 256>>>(props, cls, boxes, masks, out);

    // K2: PDL secondary of K1
    {
        cudaLaunchConfig_t cfg = {};
        cfg.gridDim  = dim3(4, 1, 1);
        cfg.blockDim = dim3(256, 1, 1);
        cfg.stream   = 0;
        cudaLaunchAttribute a[1];
        a[0].id = cudaLaunchAttributeProgrammaticStreamSerialization;
        a[0].val.programmaticStreamSerializationAllowed = 1;
        cfg.attrs = a;
        cfg.numAttrs = 1;
        cudaLaunchKernelEx(&cfg, select_kernel, props, cls, boxes, out);
    }

    // K3: PDL secondary of K2 — positive tiles only, 4 blocks each
    {
        cudaLaunchConfig_t cfg = {};
        cfg.gridDim  = dim3(BB*PP*MSPLIT, 1, 1);
        cfg.blockDim = dim3(MPX, 1, 1);
        cfg.stream   = 0;
        cudaLaunchAttribute a[1];
        a[0].id = cudaLaunchAttributeProgrammaticStreamSerialization;
        a[0].val.programmaticStreamSerializationAllowed = 1;
        cfg.attrs = a;
        cfg.numAttrs = 1;
        cudaLaunchKernelEx(&cfg, mask_kernel, masks, out);
    }
}